// round 14
// baseline (speedup 1.0000x reference)
#include <cuda_runtime.h>
#include <math.h>
#include <stdint.h>

#define NN      1024
#define KNN     8
#define D_IN    36
#define NPAIR   (NN*(NN-1)/2)    // 523776
#define EPSV    1e-5f
#define SLOPE   0.01f

// ---------------- device scratch ----------------
__device__ float g_e1[NN*32];             // edge conv 1 out
__device__ float g_e2[NN*32];             // edge conv 2 out
__device__ float g_sc[D_IN], g_sh[D_IN];  // folded BN: v = x*sc + sh
__device__ int   g_idx[NN*KNN];
__device__ float4 g_w1t1[72*32];          // ec1_w1 packed: [tt][o]
__device__ float4 g_w1t2[64*32];
__device__ float g_part[4*100*128];       // pair-stats partials
__device__ float g_m1[100], g_s1[100], g_m2[100], g_s2[100];
__device__ float g_A[NN*32];
__device__ float g_B[NN*32];
__device__ unsigned int g_done;           // last-block ticket (self-resetting)

__device__ __forceinline__ float leaky(float x){ return fmaxf(x, SLOPE*x); }
__device__ __forceinline__ int rowstart(int i){ return i*NN - ((i*(i+1))>>1); }

// tf32 helpers
__device__ __forceinline__ uint32_t to_tf32(float v){
    uint32_t r; asm("cvt.rna.tf32.f32 %0,%1;":"=r"(r):"f"(v)); return r;
}
__device__ __forceinline__ void mma_tf32(float* C, const uint32_t* A, const uint32_t* B){
    asm volatile(
      "mma.sync.aligned.m16n8k8.row.col.f32.tf32.tf32.f32 "
      "{%0,%1,%2,%3},{%4,%5,%6,%7},{%8,%9},{%0,%1,%2,%3};"
      : "+f"(C[0]),"+f"(C[1]),"+f"(C[2]),"+f"(C[3])
      : "r"(A[0]),"r"(A[1]),"r"(A[2]),"r"(A[3]),"r"(B[0]),"r"(B[1]));
}

// ==== k1: BN stats+fold (0..35) | weight pack (36..71) | cells (72..81) ====
__global__ void __launch_bounds__(512) k_stats(const float* __restrict__ feat,
        const float* __restrict__ e1w1, const float* __restrict__ e2w1,
        const float* __restrict__ bng,  const float* __restrict__ bnb,
        float* __restrict__ out_cells){
    __shared__ float ss[512], sq[512];
    int tid=threadIdx.x, bid=blockIdx.x;
    if (bid < 36){
        int f = bid;
        float s=0.f, q=0.f;
        for(int i=tid;i<NN;i+=512){ float v=feat[i*D_IN+f]; s+=v; q+=v*v; }
        ss[tid]=s; sq[tid]=q; __syncthreads();
        for(int o=256;o>0;o>>=1){
            if(tid<o){ ss[tid]+=ss[tid+o]; sq[tid]+=sq[tid+o]; }
            __syncthreads();
        }
        if(tid==0){
            float m=ss[0]*(1.f/NN);
            float var=sq[0]*(1.f/NN)-m*m;
            float sc = rsqrtf(var+EPSV)*bng[f];
            g_sc[f]=sc;
            g_sh[f]=bnb[f]-m*sc;
        }
    } else if (bid < 72){
        int t = (bid-36)*512 + tid;
        if (t < 72*32){ int tt=t>>5, o=t&31; g_w1t1[t] = *(const float4*)(e1w1 + o*288 + 4*tt); }
        if (t < 64*32){ int tt=t>>5, o=t&31; g_w1t2[t] = *(const float4*)(e2w1 + o*256 + 4*tt); }
    } else {
        int t = (bid-72)*512 + tid;
        if (t < NN*5){
            int i=t/5, c=t%5;
            out_cells[t] = feat[i*D_IN+c];
        }
    }
}

// ============ k2: kNN + edge conv 1 fused (128 x 512) ============
__global__ void __launch_bounds__(512) k_knn_e1(const float* __restrict__ feat,
        const float* __restrict__ b1,
        const float* __restrict__ w2, const float* __restrict__ b2){
    extern __shared__ char sm_[];
    const int tid=threadIdx.x, bid=blockIdx.x;
    const int w=tid>>5, lane=tid&31;
    const int n8=w>>1, h=w&1;
    const int node = bid*8 + n8;

    // ---- kNN (2 warps per node); coords normalized inline ----
    {
        float4* sxy = (float4*)sm_;
        float  (*skd)[2][8] = (float(*)[2][8])(sm_+16384);
        int    (*ski)[2][8] = (int  (*)[2][8])(sm_+16896);
        float4 sc4, sh4;
        sc4.x=__ldg(&g_sc[0]); sc4.y=__ldg(&g_sc[1]); sc4.z=__ldg(&g_sc[2]); sc4.w=__ldg(&g_sc[3]);
        sh4.x=__ldg(&g_sh[0]); sh4.y=__ldg(&g_sh[1]); sh4.z=__ldg(&g_sh[2]); sh4.w=__ldg(&g_sh[3]);
        for(int t=tid;t<NN;t+=512){
            float4 r = *(const float4*)(feat + t*D_IN);
            float4 v;
            v.x=fmaf(r.x,sc4.x,sh4.x); v.y=fmaf(r.y,sc4.y,sh4.y);
            v.z=fmaf(r.z,sc4.z,sh4.z); v.w=fmaf(r.w,sc4.w,sh4.w);
            sxy[t]=v;
        }
        __syncthreads();
        const float4 xi = sxy[node];
        float d8[8]; int id8[8];
#pragma unroll
        for(int k=0;k<8;k++){ d8[k]=3.4e38f; id8[k]=0x7fffffff; }
        float kth = 3.4e38f; int kthi = 0x7fffffff;
        for(int it=0; it<16; it++){
            int j = 512*h + it*32 + lane;
            float4 xj = sxy[j];
            float cd = fabsf(xi.x-xj.x)+fabsf(xi.y-xj.y)+fabsf(xi.z-xj.z)+fabsf(xi.w-xj.w);
            int ci = j;
            if (cd < kth || (cd==kth && ci < kthi)){
#pragma unroll
                for(int k=0;k<8;k++){
                    bool sw = (cd < d8[k]) || (cd==d8[k] && ci < id8[k]);
                    float td = sw ? d8[k] : cd; int ti = sw ? id8[k] : ci;
                    d8[k]  = sw ? cd : d8[k]; id8[k] = sw ? ci : id8[k];
                    cd=td; ci=ti;
                }
                kth = d8[7]; kthi = id8[7];
            }
        }
        for(int r=0;r<8;r++){
            float bd=d8[0]; int bi=id8[0];
#pragma unroll
            for(int off=16;off>0;off>>=1){
                float od=__shfl_xor_sync(0xffffffffu,bd,off);
                int   oi=__shfl_xor_sync(0xffffffffu,bi,off);
                if (od<bd || (od==bd && oi<bi)){ bd=od; bi=oi; }
            }
            if (lane==0){ skd[n8][h][r]=bd; ski[n8][h][r]=bi; }
            if (id8[0]==bi){
#pragma unroll
                for(int k=0;k<7;k++){ d8[k]=d8[k+1]; id8[k]=id8[k+1]; }
                d8[7]=3.4e38f; id8[7]=0x7fffffff;
            }
        }
        __syncthreads();
        if (h==0){
            float md = 3.4e38f; int mi = 0x7fffffff;
            if (lane < 16){ md = skd[n8][lane>>3][lane&7]; mi = ski[n8][lane>>3][lane&7]; }
            for(int r=0;r<8;r++){
                float bd=md; int bi=mi;
#pragma unroll
                for(int off=16;off>0;off>>=1){
                    float od=__shfl_xor_sync(0xffffffffu,bd,off);
                    int   oi=__shfl_xor_sync(0xffffffffu,bi,off);
                    if (od<bd || (od==bd && oi<bi)){ bd=od; bi=oi; }
                }
                if (lane==0) g_idx[node*KNN+r]=bi;
                if (md==bd && mi==bi){ md=3.4e38f; mi=0x7fffffff; }
            }
        }
    }
    __syncthreads();

    // ---- edge conv 1 (gather normalizes inline) ----
    {
        float4* sW  = (float4*)sm_;
        float (*sv)[288]   = (float(*)[288])(sm_+36864);
        float (*sh2)[2][32]= (float(*)[2][32])(sm_+46080);
        float (*sh1)[32]   = (float(*)[32])(sm_+48128);
        for(int t=tid;t<72*32;t+=512) sW[t]=g_w1t1[t];
        for(int t=lane;t<144;t+=32){
            int f = 18*h + (t>>3), k = t&7;
            int nb = g_idx[node*KNN+k];
            sv[n8][f*8+k] = fmaf(feat[nb*D_IN+f], __ldg(&g_sc[f]), __ldg(&g_sh[f]));
        }
        __syncthreads();
        float a0=0.f,a1=0.f,a2=0.f,a3=0.f;
        const float4* vv4 = (const float4*)sv[n8];
#pragma unroll
        for(int u=0;u<36;u++){
            int tt = 36*h+u;
            float4 wv = sW[tt*32+lane];
            float4 vv = vv4[tt];
            a0+=wv.x*vv.x; a1+=wv.y*vv.y; a2+=wv.z*vv.z; a3+=wv.w*vv.w;
        }
        sh2[n8][h][lane]=((a0+a1)+(a2+a3));
        __syncthreads();
        if (h==0){
            float acc = sh2[n8][0][lane]+sh2[n8][1][lane]+b1[lane];
            sh1[n8][lane]=leaky(acc);
            __syncwarp();
            float acc2 = b2[lane];
            const float4* w2v = (const float4*)(w2 + lane*32);
#pragma unroll
            for(int q=0;q<8;q++){
                float4 wv=w2v[q];
                acc2 += wv.x*sh1[n8][4*q]+wv.y*sh1[n8][4*q+1]+wv.z*sh1[n8][4*q+2]+wv.w*sh1[n8][4*q+3];
            }
            g_e1[node*32+lane]=leaky(acc2);
        }
    }
}

// ==== k3: edge conv 2 + stats1 + last-block stats2 (128 x 512) ====
__global__ void __launch_bounds__(512) k_e2s1(const float* __restrict__ feat,
        const float* __restrict__ b1, const float* __restrict__ w2,
        const float* __restrict__ b2){
    extern __shared__ char sm_[];
    const int tid=threadIdx.x, bid=blockIdx.x;
    const int w=tid>>5, lane=tid&31;
    const int n8=w>>1, h=w&1;
    const int node = bid*8 + n8;

    // ---- edge conv 2 ----
    {
        float4* sW  = (float4*)sm_;                         // 32768
        float (*sv)[256]   = (float(*)[256])(sm_+32768);    // 8192
        float (*sh2)[2][32]= (float(*)[2][32])(sm_+40960);  // 2048
        float (*sh1)[32]   = (float(*)[32])(sm_+43008);     // 1024
        for(int t=tid;t<64*32;t+=512) sW[t]=g_w1t2[t];
        for(int t=lane;t<128;t+=32){
            int f = 16*h + (t>>3), k = t&7;
            int nb = g_idx[node*KNN+k];
            sv[n8][f*8+k] = g_e1[nb*32+f];
        }
        __syncthreads();
        float a0=0.f,a1=0.f,a2=0.f,a3=0.f;
        const float4* vv4 = (const float4*)sv[n8];
#pragma unroll
        for(int u=0;u<32;u++){
            int tt = 32*h+u;
            float4 wv = sW[tt*32+lane];
            float4 vv = vv4[tt];
            a0+=wv.x*vv.x; a1+=wv.y*vv.y; a2+=wv.z*vv.z; a3+=wv.w*vv.w;
        }
        sh2[n8][h][lane]=((a0+a1)+(a2+a3));
        __syncthreads();
        if (h==0){
            float acc = sh2[n8][0][lane]+sh2[n8][1][lane]+b1[lane];
            sh1[n8][lane]=leaky(acc);
            __syncwarp();
            float acc2 = b2[lane];
            const float4* w2v = (const float4*)(w2 + lane*32);
#pragma unroll
            for(int q=0;q<8;q++){
                float4 wv=w2v[q];
                acc2 += wv.x*sh1[n8][4*q]+wv.y*sh1[n8][4*q+1]+wv.z*sh1[n8][4*q+2]+wv.w*sh1[n8][4*q+3];
            }
            g_e2[node*32+lane]=leaky(acc2);
        }
    }
    __syncthreads();

    // ---- stats stage 1: per-block (8 nodes) weighted partials ----
    {
        float (*srow)[100] = (float(*)[100])sm_;
        for(int t=tid;t<288;t+=512){
            int f=t%36;
            srow[t/36][f] = fmaf(feat[bid*8*D_IN + t], __ldg(&g_sc[f]), __ldg(&g_sh[f]));
        }
        for(int t=tid;t<256;t+=512) srow[t>>5][36+(t&31)] = g_e1[bid*8*32 + t];
        __syncthreads();
        for(int t=tid;t<256;t+=512) srow[t>>5][68+(t&31)] = g_e2[bid*8*32 + t];
        __syncthreads();
        if (tid < 400){
            int c = tid/100, f = tid%100;
            float acc=0.f;
#pragma unroll
            for(int nd=0;nd<8;nd++){
                int gi = bid*8+nd;
                float v = srow[nd][f];
                float wt = (c<2)? (float)(NN-1-gi) : (float)gi;
                float vv = (c&1)? v*v : v;
                acc += wt*vv;
            }
            g_part[tid*128 + bid] = acc;   // layout: [(c*100+f)][block]
        }
    }

    // ---- last-block stats stage 2 (deterministic fan-in) ----
    __syncthreads();
    __threadfence();
    __shared__ int is_last;
    if (tid==0){
        unsigned int old = atomicInc(&g_done, 127u);   // wraps to 0 at 128 -> self-reset
        is_last = (old == 127u);
    }
    __syncthreads();
    if (is_last){
        float* red = (float*)sm_;      // 400 floats
        if (tid < 400){
            const float4* p4 = (const float4*)&g_part[tid*128];
            float a0=0.f,a1=0.f,a2=0.f,a3=0.f;
#pragma unroll 8
            for(int u=0;u<32;u++){
                float4 v = __ldcg(&p4[u]);
                a0+=v.x; a1+=v.y; a2+=v.z; a3+=v.w;
            }
            red[tid] = (a0+a1)+(a2+a3);
        }
        __syncthreads();
        if (tid < 100){
            const float invP = 1.0f/(float)NPAIR;
            int f = tid;
            float m1=red[0*100+f]*invP, q1=red[1*100+f]*invP;
            float m2=red[2*100+f]*invP, q2=red[3*100+f]*invP;
            g_m1[f]=m1; g_s1[f]=rsqrtf(q1-m1*m1+EPSV);
            g_m2[f]=m2; g_s2[f]=rsqrtf(q2-m2*m2+EPSV);
        }
    }
}

// ============ k4: W1p + bias + A,B projections (128 x 512) ============
__global__ void __launch_bounds__(512) k_abk(const float* __restrict__ feat,
        const float* __restrict__ lw1, const float* __restrict__ lb1,
        const float* __restrict__ lbng, const float* __restrict__ lbnb){
    extern __shared__ char sm_[];
    const int tid=threadIdx.x, bid=blockIdx.x;
    const int w=tid>>5, lane=tid&31;
    const int n8=w>>1, h=w&1;
    const int node = bid*8 + n8;

    float* sWp = (float*)sm_;                 // 6400
    float* ssc = sWp + 6400;                  // 200
    float* ssh = ssc + 200;                   // 200
    float* spart = ssh + 200;                 // 512
    float* scc = spart + 512;                 // 32
    float (*srow)[100]  = (float(*)[100])(scc + 32);          // 800
    float (*spa)[2][32] = (float(*)[2][32])(scc + 32 + 800);  // 512
    float (*spb)[2][32] = (float(*)[2][32])(scc + 32 + 1312); // 512

    if (tid < 200){
        float m  = (tid<100)? g_m1[tid] : g_m2[tid-100];
        float sv = (tid<100)? g_s1[tid] : g_s2[tid-100];
        float sc = lbng[tid]*sv;
        ssc[tid] = sc;
        ssh[tid] = lbnb[tid]-m*sc;
    }
    __syncthreads();
    for(int t=tid;t<6400;t+=512){
        int o=t&31, f=t>>5;
        sWp[t] = lw1[o*200+f]*ssc[f];
    }
    {   // bias partials: 16 chunks x 32 outputs
        int o = tid&31, ch = tid>>5;
        int f0 = ch*12 + min(ch,8);
        int len = (ch<8)? 13 : 12;
        float acc=0.f;
        for(int u=0;u<len;u++){
            int f=f0+u;
            acc += lw1[o*200+f]*ssh[f];
        }
        spart[ch*32+o]=acc;
    }
    __syncthreads();
    if (tid<32){
        float c=lb1[tid];
#pragma unroll
        for(int ch=0;ch<16;ch++) c += spart[ch*32+tid];
        scc[tid]=c;
    }
    for(int t=tid;t<288;t+=512){
        int f=t%36;
        srow[t/36][f] = fmaf(feat[bid*8*D_IN + t], __ldg(&g_sc[f]), __ldg(&g_sh[f]));
    }
    for(int t=tid;t<256;t+=512) srow[t>>5][36+(t&31)] = g_e1[bid*8*32 + t];
    for(int t=tid;t<256;t+=512) srow[t>>5][68+(t&31)] = g_e2[bid*8*32 + t];
    __syncthreads();
    float a=0.f, b=0.f;
    for(int u=0;u<50;u++){
        int f = 50*h+u;
        float v=srow[n8][f];
        a += v*sWp[f*32+lane];
        b += v*sWp[(100+f)*32+lane];
    }
    spa[n8][h][lane]=a; spb[n8][h][lane]=b;
    __syncthreads();
    if (h==0){
        g_A[node*32+lane]=spa[n8][0][lane]+spa[n8][1][lane]+scc[lane];
        g_B[node*32+lane]=spb[n8][0][lane]+spb[n8][1][lane];
    }
}

// =====================================================================
// Pair kernel (unchanged): single-term tf32 MMA, 3 blocks/SM
// =====================================================================
#define H1STRIDE 36
__global__ void __launch_bounds__(256,3) k_pairs_tc(
        const float* __restrict__ lw2, const float* __restrict__ lb2,
        const float* __restrict__ lw3, const float* __restrict__ lb3,
        float* __restrict__ out){
    __shared__ float sh1s[8][16*H1STRIDE];
    __shared__ float sW3[64], sB3[2];
    const int warp = threadIdx.x>>5, lane = threadIdx.x&31;
    const int g = lane>>2, tig = lane&3;

    if (threadIdx.x<64) sW3[threadIdx.x]=lw3[threadIdx.x];
    if (threadIdx.x<2)  sB3[threadIdx.x]=lb3[threadIdx.x];
    __syncthreads();

    uint32_t Bhi[4][4][2];
#pragma unroll
    for(int s=0;s<4;s++){
#pragma unroll
        for(int nt=0;nt<4;nt++){
            int o = nt*8 + g;
            Bhi[s][nt][0] = to_tf32(__ldg(&lw2[o*32 + s*8 + tig]));
            Bhi[s][nt][1] = to_tf32(__ldg(&lw2[o*32 + s*8 + tig + 4]));
        }
    }
    float b2r[4][2];
#pragma unroll
    for(int nt=0;nt<4;nt++){
        b2r[nt][0]=__ldg(&lb2[nt*8+2*tig]);
        b2r[nt][1]=__ldg(&lb2[nt*8+2*tig+1]);
    }

    float* sh = sh1s[warp];
    const int pr = lane>>1, half = lane&1;
    const int tile0 = (blockIdx.x*8 + warp)*4;

    int i, j;
    {
        int p = tile0*16 + pr;
        int disc=(2*NN-1)*(2*NN-1)-8*p;
        float sqv=sqrtf((float)disc);
        i=(int)(((float)(2*NN-1)-sqv)*0.5f);
        if(i<0)i=0; if(i>NN-2)i=NN-2;
        while(i<NN-2 && rowstart(i+1)<=p) i++;
        while(i>0 && rowstart(i)>p) i--;
        j = p-rowstart(i)+i+1;
    }

#pragma unroll 1
    for(int tt=0; tt<4; tt++){
        const int base = (tile0+tt)*16;
        {
            const float4* a4 = (const float4*)(g_A + i*32 + half*16);
            const float4* b4 = (const float4*)(g_B + j*32 + half*16);
            float4* row = (float4*)(sh + pr*H1STRIDE + half*16);
#pragma unroll
            for(int q=0;q<4;q++){
                float4 av=a4[q], bv=b4[q];
                float4 hv;
                hv.x=leaky(av.x+bv.x); hv.y=leaky(av.y+bv.y);
                hv.z=leaky(av.z+bv.z); hv.w=leaky(av.w+bv.w);
                row[q]=hv;
            }
        }
        if (tt < 3){
            j += 16;
            while (j >= NN){ j = j - NN + i + 2; i++; }
        }
        __syncwarp();

        float C[4][4];
#pragma unroll
        for(int nt=0;nt<4;nt++){
            C[nt][0]=b2r[nt][0]; C[nt][1]=b2r[nt][1];
            C[nt][2]=b2r[nt][0]; C[nt][3]=b2r[nt][1];
        }
#pragma unroll
        for(int s=0;s<4;s++){
            const int f0=s*8+tig, f1=f0+4;
            float v0 = sh[ g   *H1STRIDE + f0];
            float v1 = sh[(g+8)*H1STRIDE + f0];
            float v2 = sh[ g   *H1STRIDE + f1];
            float v3 = sh[(g+8)*H1STRIDE + f1];
            uint32_t Ah[4];
            Ah[0]=to_tf32(v0); Ah[1]=to_tf32(v1);
            Ah[2]=to_tf32(v2); Ah[3]=to_tf32(v3);
#pragma unroll
            for(int nt=0;nt<4;nt++){
                mma_tf32(C[nt], Ah, Bhi[s][nt]);
            }
        }

        float y00=0.f,y01=0.f,y10=0.f,y11=0.f;
#pragma unroll
        for(int nt=0;nt<4;nt++){
            float w300=sW3[nt*8+2*tig],    w301=sW3[nt*8+2*tig+1];
            float w310=sW3[32+nt*8+2*tig], w311=sW3[32+nt*8+2*tig+1];
            float h0=leaky(C[nt][0]), h1v=leaky(C[nt][1]);
            float h2=leaky(C[nt][2]), h3=leaky(C[nt][3]);
            y00 += h0*w300 + h1v*w301;
            y01 += h0*w310 + h1v*w311;
            y10 += h2*w300 + h3*w301;
            y11 += h2*w310 + h3*w311;
        }
        y00 += __shfl_xor_sync(0xffffffffu,y00,1); y00 += __shfl_xor_sync(0xffffffffu,y00,2);
        y01 += __shfl_xor_sync(0xffffffffu,y01,1); y01 += __shfl_xor_sync(0xffffffffu,y01,2);
        y10 += __shfl_xor_sync(0xffffffffu,y10,1); y10 += __shfl_xor_sync(0xffffffffu,y10,2);
        y11 += __shfl_xor_sync(0xffffffffu,y11,1); y11 += __shfl_xor_sync(0xffffffffu,y11,2);
        if (tig==0){
            *(float2*)(out + (size_t)(base+g)*2)   = make_float2(y00+sB3[0], y01+sB3[1]);
            *(float2*)(out + (size_t)(base+g+8)*2) = make_float2(y10+sB3[0], y11+sB3[1]);
        }
        __syncwarp();
    }
}

// ---------------- launch: 5 kernels ----------------
extern "C" void kernel_launch(void* const* d_in, const int* in_sizes, int n_in,
                              void* d_out, int out_size){
    const float* feat   = (const float*)d_in[0];
    const float* bn_g   = (const float*)d_in[1];
    const float* bn_b   = (const float*)d_in[2];
    const float* ec1_w1 = (const float*)d_in[3];
    const float* ec1_b1 = (const float*)d_in[4];
    const float* ec1_w2 = (const float*)d_in[5];
    const float* ec1_b2 = (const float*)d_in[6];
    const float* ec2_w1 = (const float*)d_in[7];
    const float* ec2_b1 = (const float*)d_in[8];
    const float* ec2_w2 = (const float*)d_in[9];
    const float* ec2_b2 = (const float*)d_in[10];
    const float* lbn_g  = (const float*)d_in[11];
    const float* lbn_b  = (const float*)d_in[12];
    const float* l_w1   = (const float*)d_in[13];
    const float* l_b1   = (const float*)d_in[14];
    const float* l_w2   = (const float*)d_in[15];
    const float* l_b2   = (const float*)d_in[16];
    const float* l_w3   = (const float*)d_in[17];
    const float* l_b3   = (const float*)d_in[18];
    float* out = (float*)d_out;

    static int attr_done = 0;
    if (!attr_done){
        cudaFuncSetAttribute(k_knn_e1, cudaFuncAttributeMaxDynamicSharedMemorySize, 49152);
        cudaFuncSetAttribute(k_e2s1,   cudaFuncAttributeMaxDynamicSharedMemorySize, 45056);
        cudaFuncSetAttribute(k_abk,    cudaFuncAttributeMaxDynamicSharedMemorySize, 36864);
        attr_done = 1;
    }

    k_stats  <<<82, 512>>>(feat, ec1_w1, ec2_w1, bn_g, bn_b, out + (size_t)2*NPAIR);
    k_knn_e1 <<<128, 512, 49152>>>(feat, ec1_b1, ec1_w2, ec1_b2);
    k_e2s1   <<<128, 512, 45056>>>(feat, ec2_b1, ec2_w2, ec2_b2);
    k_abk    <<<128, 512, 36864>>>(feat, l_w1, l_b1, lbn_g, lbn_b);
    k_pairs_tc<<<1023, 256>>>(l_w2, l_b2, l_w3, l_b3, out);
}

// round 15
// speedup vs baseline: 1.1514x; 1.1514x over previous
#include <cuda_runtime.h>
#include <math.h>
#include <stdint.h>

#define NN      1024
#define KNN     8
#define D_IN    36
#define NPAIR   (NN*(NN-1)/2)    // 523776
#define EPSV    1e-5f
#define SLOPE   0.01f

// ---------------- device scratch ----------------
__device__ float g_e1[NN*32];             // edge conv 1 out
__device__ float g_e2[NN*32];             // edge conv 2 out
__device__ float g_sc[D_IN], g_sh[D_IN];  // folded feature-BN: v = x*sc + sh
__device__ int   g_idx[NN*KNN];
__device__ float4 g_w1t1[72*32];          // ec1_w1 packed: [tt][o]
__device__ float4 g_w1t2[64*32];
__device__ float g_part[4*100*128];       // pair-stats partials
__device__ float g_W1p[200*32];           // BN-scaled l_w1 (written by k_stats2)
__device__ float g_ssh[200];              // pair-BN shift (for bias fold)
__device__ float g_A[NN*32];
__device__ float g_B[NN*32];

__device__ __forceinline__ float leaky(float x){ return fmaxf(x, SLOPE*x); }
__device__ __forceinline__ int rowstart(int i){ return i*NN - ((i*(i+1))>>1); }

// tf32 helpers
__device__ __forceinline__ uint32_t to_tf32(float v){
    uint32_t r; asm("cvt.rna.tf32.f32 %0,%1;":"=r"(r):"f"(v)); return r;
}
__device__ __forceinline__ void mma_tf32(float* C, const uint32_t* A, const uint32_t* B){
    asm volatile(
      "mma.sync.aligned.m16n8k8.row.col.f32.tf32.tf32.f32 "
      "{%0,%1,%2,%3},{%4,%5,%6,%7},{%8,%9},{%0,%1,%2,%3};"
      : "+f"(C[0]),"+f"(C[1]),"+f"(C[2]),"+f"(C[3])
      : "r"(A[0]),"r"(A[1]),"r"(A[2]),"r"(A[3]),"r"(B[0]),"r"(B[1]));
}

// ==== k1: BN stats+fold (0..35) | weight pack (36..71) | cells (72..81) ====
__global__ void __launch_bounds__(512) k_stats(const float* __restrict__ feat,
        const float* __restrict__ e1w1, const float* __restrict__ e2w1,
        const float* __restrict__ bng,  const float* __restrict__ bnb,
        float* __restrict__ out_cells){
    __shared__ float ss[512], sq[512];
    int tid=threadIdx.x, bid=blockIdx.x;
    if (bid < 36){
        int f = bid;
        float s=0.f, q=0.f;
        for(int i=tid;i<NN;i+=512){ float v=feat[i*D_IN+f]; s+=v; q+=v*v; }
        ss[tid]=s; sq[tid]=q; __syncthreads();
        for(int o=256;o>0;o>>=1){
            if(tid<o){ ss[tid]+=ss[tid+o]; sq[tid]+=sq[tid+o]; }
            __syncthreads();
        }
        if(tid==0){
            float m=ss[0]*(1.f/NN);
            float var=sq[0]*(1.f/NN)-m*m;
            float sc = rsqrtf(var+EPSV)*bng[f];
            g_sc[f]=sc;
            g_sh[f]=bnb[f]-m*sc;
        }
    } else if (bid < 72){
        int t = (bid-36)*512 + tid;
        if (t < 72*32){ int tt=t>>5, o=t&31; g_w1t1[t] = *(const float4*)(e1w1 + o*288 + 4*tt); }
        if (t < 64*32){ int tt=t>>5, o=t&31; g_w1t2[t] = *(const float4*)(e2w1 + o*256 + 4*tt); }
    } else {
        int t = (bid-72)*512 + tid;
        if (t < NN*5){
            int i=t/5, c=t%5;
            out_cells[t] = feat[i*D_IN+c];
        }
    }
}

// ============ k2: kNN + edge conv 1 fused (128 x 512) ============
__global__ void __launch_bounds__(512) k_knn_e1(const float* __restrict__ feat,
        const float* __restrict__ b1,
        const float* __restrict__ w2, const float* __restrict__ b2){
    extern __shared__ char sm_[];
    const int tid=threadIdx.x, bid=blockIdx.x;
    const int w=tid>>5, lane=tid&31;
    const int n8=w>>1, h=w&1;
    const int node = bid*8 + n8;

    // ---- kNN (2 warps per node); coords normalized inline ----
    {
        float4* sxy = (float4*)sm_;
        float  (*skd)[2][8] = (float(*)[2][8])(sm_+16384);
        int    (*ski)[2][8] = (int  (*)[2][8])(sm_+16896);
        float4 sc4, sh4;
        sc4.x=__ldg(&g_sc[0]); sc4.y=__ldg(&g_sc[1]); sc4.z=__ldg(&g_sc[2]); sc4.w=__ldg(&g_sc[3]);
        sh4.x=__ldg(&g_sh[0]); sh4.y=__ldg(&g_sh[1]); sh4.z=__ldg(&g_sh[2]); sh4.w=__ldg(&g_sh[3]);
        for(int t=tid;t<NN;t+=512){
            float4 r = *(const float4*)(feat + t*D_IN);
            float4 v;
            v.x=fmaf(r.x,sc4.x,sh4.x); v.y=fmaf(r.y,sc4.y,sh4.y);
            v.z=fmaf(r.z,sc4.z,sh4.z); v.w=fmaf(r.w,sc4.w,sh4.w);
            sxy[t]=v;
        }
        __syncthreads();
        const float4 xi = sxy[node];
        float d8[8]; int id8[8];
#pragma unroll
        for(int k=0;k<8;k++){ d8[k]=3.4e38f; id8[k]=0x7fffffff; }
        float kth = 3.4e38f; int kthi = 0x7fffffff;
        for(int it=0; it<16; it++){
            int j = 512*h + it*32 + lane;
            float4 xj = sxy[j];
            float cd = fabsf(xi.x-xj.x)+fabsf(xi.y-xj.y)+fabsf(xi.z-xj.z)+fabsf(xi.w-xj.w);
            int ci = j;
            if (cd < kth || (cd==kth && ci < kthi)){
#pragma unroll
                for(int k=0;k<8;k++){
                    bool sw = (cd < d8[k]) || (cd==d8[k] && ci < id8[k]);
                    float td = sw ? d8[k] : cd; int ti = sw ? id8[k] : ci;
                    d8[k]  = sw ? cd : d8[k]; id8[k] = sw ? ci : id8[k];
                    cd=td; ci=ti;
                }
                kth = d8[7]; kthi = id8[7];
            }
        }
        for(int r=0;r<8;r++){
            float bd=d8[0]; int bi=id8[0];
#pragma unroll
            for(int off=16;off>0;off>>=1){
                float od=__shfl_xor_sync(0xffffffffu,bd,off);
                int   oi=__shfl_xor_sync(0xffffffffu,bi,off);
                if (od<bd || (od==bd && oi<bi)){ bd=od; bi=oi; }
            }
            if (lane==0){ skd[n8][h][r]=bd; ski[n8][h][r]=bi; }
            if (id8[0]==bi){
#pragma unroll
                for(int k=0;k<7;k++){ d8[k]=d8[k+1]; id8[k]=id8[k+1]; }
                d8[7]=3.4e38f; id8[7]=0x7fffffff;
            }
        }
        __syncthreads();
        if (h==0){
            float md = 3.4e38f; int mi = 0x7fffffff;
            if (lane < 16){ md = skd[n8][lane>>3][lane&7]; mi = ski[n8][lane>>3][lane&7]; }
            for(int r=0;r<8;r++){
                float bd=md; int bi=mi;
#pragma unroll
                for(int off=16;off>0;off>>=1){
                    float od=__shfl_xor_sync(0xffffffffu,bd,off);
                    int   oi=__shfl_xor_sync(0xffffffffu,bi,off);
                    if (od<bd || (od==bd && oi<bi)){ bd=od; bi=oi; }
                }
                if (lane==0) g_idx[node*KNN+r]=bi;
                if (md==bd && mi==bi){ md=3.4e38f; mi=0x7fffffff; }
            }
        }
    }
    __syncthreads();

    // ---- edge conv 1 (gather normalizes inline) ----
    {
        float4* sW  = (float4*)sm_;
        float (*sv)[288]   = (float(*)[288])(sm_+36864);
        float (*sh2)[2][32]= (float(*)[2][32])(sm_+46080);
        float (*sh1)[32]   = (float(*)[32])(sm_+48128);
        for(int t=tid;t<72*32;t+=512) sW[t]=g_w1t1[t];
        for(int t=lane;t<144;t+=32){
            int f = 18*h + (t>>3), k = t&7;
            int nb = g_idx[node*KNN+k];
            sv[n8][f*8+k] = fmaf(feat[nb*D_IN+f], __ldg(&g_sc[f]), __ldg(&g_sh[f]));
        }
        __syncthreads();
        float a0=0.f,a1=0.f,a2=0.f,a3=0.f;
        const float4* vv4 = (const float4*)sv[n8];
#pragma unroll
        for(int u=0;u<36;u++){
            int tt = 36*h+u;
            float4 wv = sW[tt*32+lane];
            float4 vv = vv4[tt];
            a0+=wv.x*vv.x; a1+=wv.y*vv.y; a2+=wv.z*vv.z; a3+=wv.w*vv.w;
        }
        sh2[n8][h][lane]=((a0+a1)+(a2+a3));
        __syncthreads();
        if (h==0){
            float acc = sh2[n8][0][lane]+sh2[n8][1][lane]+b1[lane];
            sh1[n8][lane]=leaky(acc);
            __syncwarp();
            float acc2 = b2[lane];
            const float4* w2v = (const float4*)(w2 + lane*32);
#pragma unroll
            for(int q=0;q<8;q++){
                float4 wv=w2v[q];
                acc2 += wv.x*sh1[n8][4*q]+wv.y*sh1[n8][4*q+1]+wv.z*sh1[n8][4*q+2]+wv.w*sh1[n8][4*q+3];
            }
            g_e1[node*32+lane]=leaky(acc2);
        }
    }
}

// ============ k3: edge conv 2 + stats stage 1 (128 x 512) ============
__global__ void __launch_bounds__(512) k_e2s1(const float* __restrict__ feat,
        const float* __restrict__ b1, const float* __restrict__ w2,
        const float* __restrict__ b2){
    extern __shared__ char sm_[];
    const int tid=threadIdx.x, bid=blockIdx.x;
    const int w=tid>>5, lane=tid&31;
    const int n8=w>>1, h=w&1;
    const int node = bid*8 + n8;

    // ---- edge conv 2 ----
    {
        float4* sW  = (float4*)sm_;                         // 32768
        float (*sv)[256]   = (float(*)[256])(sm_+32768);    // 8192
        float (*sh2)[2][32]= (float(*)[2][32])(sm_+40960);  // 2048
        float (*sh1)[32]   = (float(*)[32])(sm_+43008);     // 1024
        for(int t=tid;t<64*32;t+=512) sW[t]=g_w1t2[t];
        for(int t=lane;t<128;t+=32){
            int f = 16*h + (t>>3), k = t&7;
            int nb = g_idx[node*KNN+k];
            sv[n8][f*8+k] = g_e1[nb*32+f];
        }
        __syncthreads();
        float a0=0.f,a1=0.f,a2=0.f,a3=0.f;
        const float4* vv4 = (const float4*)sv[n8];
#pragma unroll
        for(int u=0;u<32;u++){
            int tt = 32*h+u;
            float4 wv = sW[tt*32+lane];
            float4 vv = vv4[tt];
            a0+=wv.x*vv.x; a1+=wv.y*vv.y; a2+=wv.z*vv.z; a3+=wv.w*vv.w;
        }
        sh2[n8][h][lane]=((a0+a1)+(a2+a3));
        __syncthreads();
        if (h==0){
            float acc = sh2[n8][0][lane]+sh2[n8][1][lane]+b1[lane];
            sh1[n8][lane]=leaky(acc);
            __syncwarp();
            float acc2 = b2[lane];
            const float4* w2v = (const float4*)(w2 + lane*32);
#pragma unroll
            for(int q=0;q<8;q++){
                float4 wv=w2v[q];
                acc2 += wv.x*sh1[n8][4*q]+wv.y*sh1[n8][4*q+1]+wv.z*sh1[n8][4*q+2]+wv.w*sh1[n8][4*q+3];
            }
            g_e2[node*32+lane]=leaky(acc2);
        }
    }
    __syncthreads();

    // ---- stats stage 1: per-block (8 nodes) weighted partials ----
    {
        float (*srow)[100] = (float(*)[100])sm_;
        for(int t=tid;t<288;t+=512){
            int f=t%36;
            srow[t/36][f] = fmaf(feat[bid*8*D_IN + t], __ldg(&g_sc[f]), __ldg(&g_sh[f]));
        }
        for(int t=tid;t<256;t+=512) srow[t>>5][36+(t&31)] = g_e1[bid*8*32 + t];
        __syncthreads();
        for(int t=tid;t<256;t+=512) srow[t>>5][68+(t&31)] = g_e2[bid*8*32 + t];
        __syncthreads();
        if (tid < 400){
            int c = tid/100, f = tid%100;
            float acc=0.f;
#pragma unroll
            for(int nd=0;nd<8;nd++){
                int gi = bid*8+nd;
                float v = srow[nd][f];
                float wt = (c<2)? (float)(NN-1-gi) : (float)gi;
                float vv = (c&1)? v*v : v;
                acc += wt*vv;
            }
            g_part[(c*100+f)*128 + bid] = acc;
        }
    }
}

// ==== k4: stats stage 2 + W1p/ssh precompute (100 x 512) ====
__global__ void __launch_bounds__(512) k_stats2(const float* __restrict__ lw1,
        const float* __restrict__ lbng, const float* __restrict__ lbnb){
    __shared__ float red[512];
    __shared__ float sc2[2];
    const int tid=threadIdx.x, f=blockIdx.x;
    int c = tid>>7, idx = tid&127;
    red[tid] = g_part[(c*100+f)*128 + idx];
    __syncthreads();
    for(int o=64;o>0;o>>=1){
        if ((tid&127) < o) red[tid] += red[tid+o];
        __syncthreads();
    }
    if (tid==0){
        const float invP = 1.0f/(float)NPAIR;
        float m1=red[0]*invP,   q1=red[128]*invP;
        float m2=red[256]*invP, q2=red[384]*invP;
        float s1 = rsqrtf(q1-m1*m1+EPSV);
        float s2 = rsqrtf(q2-m2*m2+EPSV);
        float scA = lbng[f]*s1;
        float scB = lbng[100+f]*s2;
        sc2[0]=scA; sc2[1]=scB;
        g_ssh[f]     = lbnb[f]    -m1*scA;
        g_ssh[100+f] = lbnb[100+f]-m2*scB;
    }
    __syncthreads();
    if (tid < 64){
        int half = tid>>5, o = tid&31;
        int fe = f + 100*half;
        g_W1p[fe*32+o] = lw1[o*200+fe]*sc2[half];
    }
}

// ============ k5: A,B projections + coalesced bias (128 x 512) ============
__global__ void __launch_bounds__(512) k_abk(const float* __restrict__ feat,
        const float* __restrict__ lw1, const float* __restrict__ lb1){
    extern __shared__ char sm_[];
    const int tid=threadIdx.x, bid=blockIdx.x;
    const int w=tid>>5, lane=tid&31;
    const int n8=w>>1, h=w&1;
    const int node = bid*8 + n8;

    float* sWp = (float*)sm_;                 // 6400
    float* sshs = sWp + 6400;                 // 200
    float* scc = sshs + 200;                  // 32
    float (*srow)[100]  = (float(*)[100])(scc + 32);          // 800
    float (*spa)[2][32] = (float(*)[2][32])(scc + 32 + 800);  // 512
    float (*spb)[2][32] = (float(*)[2][32])(scc + 32 + 1312); // 512

    // ---- stage precomputed W1p (coalesced float4) + ssh + node rows ----
    {
        float4* d4 = (float4*)sWp;
        const float4* s4 = (const float4*)g_W1p;
        for(int t=tid;t<1600;t+=512) d4[t]=s4[t];
    }
    if (tid < 200) sshs[tid]=g_ssh[tid];
    for(int t=tid;t<288;t+=512){
        int f=t%36;
        srow[t/36][f] = fmaf(feat[bid*8*D_IN + t], __ldg(&g_sc[f]), __ldg(&g_sh[f]));
    }
    for(int t=tid;t<256;t+=512) srow[t>>5][36+(t&31)] = g_e1[bid*8*32 + t];
    for(int t=tid;t<256;t+=512) srow[t>>5][68+(t&31)] = g_e2[bid*8*32 + t];
    __syncthreads();

    // ---- folded bias: warp w computes outputs 2w, 2w+1 (coalesced lw1 reads) ----
#pragma unroll
    for(int oo=0;oo<2;oo++){
        int o = w*2 + oo;
        float acc = 0.f;
#pragma unroll
        for(int k=0;k<7;k++){
            int f = lane + 32*k;
            if (f < 200) acc += lw1[o*200+f]*sshs[f];
        }
#pragma unroll
        for(int off=16;off>0;off>>=1) acc += __shfl_xor_sync(0xffffffffu,acc,off);
        if (lane==0) scc[o]=lb1[o]+acc;
    }
    __syncthreads();

    // ---- projections ----
    float a=0.f, b=0.f;
    for(int u=0;u<50;u++){
        int f = 50*h+u;
        float v=srow[n8][f];
        a += v*sWp[f*32+lane];
        b += v*sWp[(100+f)*32+lane];
    }
    spa[n8][h][lane]=a; spb[n8][h][lane]=b;
    __syncthreads();
    if (h==0){
        g_A[node*32+lane]=spa[n8][0][lane]+spa[n8][1][lane]+scc[lane];
        g_B[node*32+lane]=spb[n8][0][lane]+spb[n8][1][lane];
    }
}

// =====================================================================
// Pair kernel (unchanged): single-term tf32 MMA, 3 blocks/SM
// =====================================================================
#define H1STRIDE 36
__global__ void __launch_bounds__(256,3) k_pairs_tc(
        const float* __restrict__ lw2, const float* __restrict__ lb2,
        const float* __restrict__ lw3, const float* __restrict__ lb3,
        float* __restrict__ out){
    __shared__ float sh1s[8][16*H1STRIDE];
    __shared__ float sW3[64], sB3[2];
    const int warp = threadIdx.x>>5, lane = threadIdx.x&31;
    const int g = lane>>2, tig = lane&3;

    if (threadIdx.x<64) sW3[threadIdx.x]=lw3[threadIdx.x];
    if (threadIdx.x<2)  sB3[threadIdx.x]=lb3[threadIdx.x];
    __syncthreads();

    uint32_t Bhi[4][4][2];
#pragma unroll
    for(int s=0;s<4;s++){
#pragma unroll
        for(int nt=0;nt<4;nt++){
            int o = nt*8 + g;
            Bhi[s][nt][0] = to_tf32(__ldg(&lw2[o*32 + s*8 + tig]));
            Bhi[s][nt][1] = to_tf32(__ldg(&lw2[o*32 + s*8 + tig + 4]));
        }
    }
    float b2r[4][2];
#pragma unroll
    for(int nt=0;nt<4;nt++){
        b2r[nt][0]=__ldg(&lb2[nt*8+2*tig]);
        b2r[nt][1]=__ldg(&lb2[nt*8+2*tig+1]);
    }

    float* sh = sh1s[warp];
    const int pr = lane>>1, half = lane&1;
    const int tile0 = (blockIdx.x*8 + warp)*4;

    int i, j;
    {
        int p = tile0*16 + pr;
        int disc=(2*NN-1)*(2*NN-1)-8*p;
        float sqv=sqrtf((float)disc);
        i=(int)(((float)(2*NN-1)-sqv)*0.5f);
        if(i<0)i=0; if(i>NN-2)i=NN-2;
        while(i<NN-2 && rowstart(i+1)<=p) i++;
        while(i>0 && rowstart(i)>p) i--;
        j = p-rowstart(i)+i+1;
    }

#pragma unroll 1
    for(int tt=0; tt<4; tt++){
        const int base = (tile0+tt)*16;
        {
            const float4* a4 = (const float4*)(g_A + i*32 + half*16);
            const float4* b4 = (const float4*)(g_B + j*32 + half*16);
            float4* row = (float4*)(sh + pr*H1STRIDE + half*16);
#pragma unroll
            for(int q=0;q<4;q++){
                float4 av=a4[q], bv=b4[q];
                float4 hv;
                hv.x=leaky(av.x+bv.x); hv.y=leaky(av.y+bv.y);
                hv.z=leaky(av.z+bv.z); hv.w=leaky(av.w+bv.w);
                row[q]=hv;
            }
        }
        if (tt < 3){
            j += 16;
            while (j >= NN){ j = j - NN + i + 2; i++; }
        }
        __syncwarp();

        float C[4][4];
#pragma unroll
        for(int nt=0;nt<4;nt++){
            C[nt][0]=b2r[nt][0]; C[nt][1]=b2r[nt][1];
            C[nt][2]=b2r[nt][0]; C[nt][3]=b2r[nt][1];
        }
#pragma unroll
        for(int s=0;s<4;s++){
            const int f0=s*8+tig, f1=f0+4;
            float v0 = sh[ g   *H1STRIDE + f0];
            float v1 = sh[(g+8)*H1STRIDE + f0];
            float v2 = sh[ g   *H1STRIDE + f1];
            float v3 = sh[(g+8)*H1STRIDE + f1];
            uint32_t Ah[4];
            Ah[0]=to_tf32(v0); Ah[1]=to_tf32(v1);
            Ah[2]=to_tf32(v2); Ah[3]=to_tf32(v3);
#pragma unroll
            for(int nt=0;nt<4;nt++){
                mma_tf32(C[nt], Ah, Bhi[s][nt]);
            }
        }

        float y00=0.f,y01=0.f,y10=0.f,y11=0.f;
#pragma unroll
        for(int nt=0;nt<4;nt++){
            float w300=sW3[nt*8+2*tig],    w301=sW3[nt*8+2*tig+1];
            float w310=sW3[32+nt*8+2*tig], w311=sW3[32+nt*8+2*tig+1];
            float h0=leaky(C[nt][0]), h1v=leaky(C[nt][1]);
            float h2=leaky(C[nt][2]), h3=leaky(C[nt][3]);
            y00 += h0*w300 + h1v*w301;
            y01 += h0*w310 + h1v*w311;
            y10 += h2*w300 + h3*w301;
            y11 += h2*w310 + h3*w311;
        }
        y00 += __shfl_xor_sync(0xffffffffu,y00,1); y00 += __shfl_xor_sync(0xffffffffu,y00,2);
        y01 += __shfl_xor_sync(0xffffffffu,y01,1); y01 += __shfl_xor_sync(0xffffffffu,y01,2);
        y10 += __shfl_xor_sync(0xffffffffu,y10,1); y10 += __shfl_xor_sync(0xffffffffu,y10,2);
        y11 += __shfl_xor_sync(0xffffffffu,y11,1); y11 += __shfl_xor_sync(0xffffffffu,y11,2);
        if (tig==0){
            *(float2*)(out + (size_t)(base+g)*2)   = make_float2(y00+sB3[0], y01+sB3[1]);
            *(float2*)(out + (size_t)(base+g+8)*2) = make_float2(y10+sB3[0], y11+sB3[1]);
        }
        __syncwarp();
    }
}

// ---------------- launch: 6 kernels ----------------
extern "C" void kernel_launch(void* const* d_in, const int* in_sizes, int n_in,
                              void* d_out, int out_size){
    const float* feat   = (const float*)d_in[0];
    const float* bn_g   = (const float*)d_in[1];
    const float* bn_b   = (const float*)d_in[2];
    const float* ec1_w1 = (const float*)d_in[3];
    const float* ec1_b1 = (const float*)d_in[4];
    const float* ec1_w2 = (const float*)d_in[5];
    const float* ec1_b2 = (const float*)d_in[6];
    const float* ec2_w1 = (const float*)d_in[7];
    const float* ec2_b1 = (const float*)d_in[8];
    const float* ec2_w2 = (const float*)d_in[9];
    const float* ec2_b2 = (const float*)d_in[10];
    const float* lbn_g  = (const float*)d_in[11];
    const float* lbn_b  = (const float*)d_in[12];
    const float* l_w1   = (const float*)d_in[13];
    const float* l_b1   = (const float*)d_in[14];
    const float* l_w2   = (const float*)d_in[15];
    const float* l_b2   = (const float*)d_in[16];
    const float* l_w3   = (const float*)d_in[17];
    const float* l_b3   = (const float*)d_in[18];
    float* out = (float*)d_out;

    static int attr_done = 0;
    if (!attr_done){
        cudaFuncSetAttribute(k_knn_e1, cudaFuncAttributeMaxDynamicSharedMemorySize, 49152);
        cudaFuncSetAttribute(k_e2s1,   cudaFuncAttributeMaxDynamicSharedMemorySize, 45056);
        cudaFuncSetAttribute(k_abk,    cudaFuncAttributeMaxDynamicSharedMemorySize, 36864);
        attr_done = 1;
    }

    k_stats  <<<82, 512>>>(feat, ec1_w1, ec2_w1, bn_g, bn_b, out + (size_t)2*NPAIR);
    k_knn_e1 <<<128, 512, 49152>>>(feat, ec1_b1, ec1_w2, ec1_b2);
    k_e2s1   <<<128, 512, 45056>>>(feat, ec2_b1, ec2_w2, ec2_b2);
    k_stats2 <<<100, 512>>>(l_w1, lbn_g, lbn_b);
    k_abk    <<<128, 512, 36864>>>(feat, l_w1, l_b1);
    k_pairs_tc<<<1023, 256>>>(l_w2, l_b2, l_w3, l_b3, out);
}

// round 16
// speedup vs baseline: 1.1857x; 1.0297x over previous
#include <cuda_runtime.h>
#include <math.h>
#include <stdint.h>

#define NN      1024
#define KNN     8
#define D_IN    36
#define NPAIR   (NN*(NN-1)/2)    // 523776
#define EPSV    1e-5f
#define SLOPE   0.01f

// ---------------- device scratch ----------------
__device__ float g_e1[NN*32];             // edge conv 1 out
__device__ float g_e2[NN*32];             // edge conv 2 out
__device__ float g_sc[D_IN], g_sh[D_IN];  // folded feature-BN: v = x*sc + sh
__device__ int   g_idx[NN*KNN];
__device__ float4 g_w1t1[72*32];          // ec1_w1 packed: [tt][o]
__device__ float4 g_w1t2[64*32];
__device__ float g_part[4*100*128];       // pair-stats partials
__device__ float g_W1p[200*32];           // BN-scaled l_w1 (written by k_stats2)
__device__ float g_ssh[200];              // pair-BN shift (for bias fold)
__device__ float g_A[NN*32];
__device__ float g_B[NN*32];

__device__ __forceinline__ float leaky(float x){ return fmaxf(x, SLOPE*x); }
__device__ __forceinline__ int rowstart(int i){ return i*NN - ((i*(i+1))>>1); }

// tf32 helpers
__device__ __forceinline__ uint32_t to_tf32(float v){
    uint32_t r; asm("cvt.rna.tf32.f32 %0,%1;":"=r"(r):"f"(v)); return r;
}
__device__ __forceinline__ void mma_tf32(float* C, const uint32_t* A, const uint32_t* B){
    asm volatile(
      "mma.sync.aligned.m16n8k8.row.col.f32.tf32.tf32.f32 "
      "{%0,%1,%2,%3},{%4,%5,%6,%7},{%8,%9},{%0,%1,%2,%3};"
      : "+f"(C[0]),"+f"(C[1]),"+f"(C[2]),"+f"(C[3])
      : "r"(A[0]),"r"(A[1]),"r"(A[2]),"r"(A[3]),"r"(B[0]),"r"(B[1]));
}

// ==== k1: BN stats+fold (0..35) | weight pack (36..71) | cells (72..81) ====
__global__ void __launch_bounds__(512) k_stats(const float* __restrict__ feat,
        const float* __restrict__ e1w1, const float* __restrict__ e2w1,
        const float* __restrict__ bng,  const float* __restrict__ bnb,
        float* __restrict__ out_cells){
    __shared__ float ss[512], sq[512];
    int tid=threadIdx.x, bid=blockIdx.x;
    if (bid < 36){
        int f = bid;
        float s=0.f, q=0.f;
        for(int i=tid;i<NN;i+=512){ float v=feat[i*D_IN+f]; s+=v; q+=v*v; }
        ss[tid]=s; sq[tid]=q; __syncthreads();
        for(int o=256;o>0;o>>=1){
            if(tid<o){ ss[tid]+=ss[tid+o]; sq[tid]+=sq[tid+o]; }
            __syncthreads();
        }
        if(tid==0){
            float m=ss[0]*(1.f/NN);
            float var=sq[0]*(1.f/NN)-m*m;
            float sc = rsqrtf(var+EPSV)*bng[f];
            g_sc[f]=sc;
            g_sh[f]=bnb[f]-m*sc;
        }
    } else if (bid < 72){
        int t = (bid-36)*512 + tid;
        if (t < 72*32){ int tt=t>>5, o=t&31; g_w1t1[t] = *(const float4*)(e1w1 + o*288 + 4*tt); }
        if (t < 64*32){ int tt=t>>5, o=t&31; g_w1t2[t] = *(const float4*)(e2w1 + o*256 + 4*tt); }
    } else {
        int t = (bid-72)*512 + tid;
        if (t < NN*5){
            int i=t/5, c=t%5;
            out_cells[t] = feat[i*D_IN+c];
        }
    }
}

// ============ k2: kNN + edge conv 1 fused (128 x 512) ============
__global__ void __launch_bounds__(512) k_knn_e1(const float* __restrict__ feat,
        const float* __restrict__ b1,
        const float* __restrict__ w2, const float* __restrict__ b2){
    extern __shared__ char sm_[];
    const int tid=threadIdx.x, bid=blockIdx.x;
    const int w=tid>>5, lane=tid&31;
    const int n8=w>>1, h=w&1;
    const int node = bid*8 + n8;

    // ---- kNN (2 warps per node); coords normalized inline ----
    {
        float4* sxy = (float4*)sm_;
        float  (*skd)[2][8] = (float(*)[2][8])(sm_+16384);
        int    (*ski)[2][8] = (int  (*)[2][8])(sm_+16896);
        float4 sc4, sh4;
        sc4.x=__ldg(&g_sc[0]); sc4.y=__ldg(&g_sc[1]); sc4.z=__ldg(&g_sc[2]); sc4.w=__ldg(&g_sc[3]);
        sh4.x=__ldg(&g_sh[0]); sh4.y=__ldg(&g_sh[1]); sh4.z=__ldg(&g_sh[2]); sh4.w=__ldg(&g_sh[3]);
        for(int t=tid;t<NN;t+=512){
            float4 r = *(const float4*)(feat + t*D_IN);
            float4 v;
            v.x=fmaf(r.x,sc4.x,sh4.x); v.y=fmaf(r.y,sc4.y,sh4.y);
            v.z=fmaf(r.z,sc4.z,sh4.z); v.w=fmaf(r.w,sc4.w,sh4.w);
            sxy[t]=v;
        }
        __syncthreads();
        const float4 xi = sxy[node];
        float d8[8]; int id8[8];
#pragma unroll
        for(int k=0;k<8;k++){ d8[k]=3.4e38f; id8[k]=0x7fffffff; }
        float kth = 3.4e38f; int kthi = 0x7fffffff;
        for(int it=0; it<16; it++){
            int j = 512*h + it*32 + lane;
            float4 xj = sxy[j];
            float cd = fabsf(xi.x-xj.x)+fabsf(xi.y-xj.y)+fabsf(xi.z-xj.z)+fabsf(xi.w-xj.w);
            int ci = j;
            if (cd < kth || (cd==kth && ci < kthi)){
#pragma unroll
                for(int k=0;k<8;k++){
                    bool sw = (cd < d8[k]) || (cd==d8[k] && ci < id8[k]);
                    float td = sw ? d8[k] : cd; int ti = sw ? id8[k] : ci;
                    d8[k]  = sw ? cd : d8[k]; id8[k] = sw ? ci : id8[k];
                    cd=td; ci=ti;
                }
                kth = d8[7]; kthi = id8[7];
            }
        }
        for(int r=0;r<8;r++){
            float bd=d8[0]; int bi=id8[0];
#pragma unroll
            for(int off=16;off>0;off>>=1){
                float od=__shfl_xor_sync(0xffffffffu,bd,off);
                int   oi=__shfl_xor_sync(0xffffffffu,bi,off);
                if (od<bd || (od==bd && oi<bi)){ bd=od; bi=oi; }
            }
            if (lane==0){ skd[n8][h][r]=bd; ski[n8][h][r]=bi; }
            if (id8[0]==bi){
#pragma unroll
                for(int k=0;k<7;k++){ d8[k]=d8[k+1]; id8[k]=id8[k+1]; }
                d8[7]=3.4e38f; id8[7]=0x7fffffff;
            }
        }
        __syncthreads();
        if (h==0){
            float md = 3.4e38f; int mi = 0x7fffffff;
            if (lane < 16){ md = skd[n8][lane>>3][lane&7]; mi = ski[n8][lane>>3][lane&7]; }
            for(int r=0;r<8;r++){
                float bd=md; int bi=mi;
#pragma unroll
                for(int off=16;off>0;off>>=1){
                    float od=__shfl_xor_sync(0xffffffffu,bd,off);
                    int   oi=__shfl_xor_sync(0xffffffffu,bi,off);
                    if (od<bd || (od==bd && oi<bi)){ bd=od; bi=oi; }
                }
                if (lane==0) g_idx[node*KNN+r]=bi;
                if (md==bd && mi==bi){ md=3.4e38f; mi=0x7fffffff; }
            }
        }
    }
    __syncthreads();

    // ---- edge conv 1 (gather normalizes inline) ----
    {
        float4* sW  = (float4*)sm_;
        float (*sv)[288]   = (float(*)[288])(sm_+36864);
        float (*sh2)[2][32]= (float(*)[2][32])(sm_+46080);
        float (*sh1)[32]   = (float(*)[32])(sm_+48128);
        for(int t=tid;t<72*32;t+=512) sW[t]=g_w1t1[t];
        for(int t=lane;t<144;t+=32){
            int f = 18*h + (t>>3), k = t&7;
            int nb = g_idx[node*KNN+k];
            sv[n8][f*8+k] = fmaf(feat[nb*D_IN+f], __ldg(&g_sc[f]), __ldg(&g_sh[f]));
        }
        __syncthreads();
        float a0=0.f,a1=0.f,a2=0.f,a3=0.f;
        const float4* vv4 = (const float4*)sv[n8];
#pragma unroll
        for(int u=0;u<36;u++){
            int tt = 36*h+u;
            float4 wv = sW[tt*32+lane];
            float4 vv = vv4[tt];
            a0+=wv.x*vv.x; a1+=wv.y*vv.y; a2+=wv.z*vv.z; a3+=wv.w*vv.w;
        }
        sh2[n8][h][lane]=((a0+a1)+(a2+a3));
        __syncthreads();
        if (h==0){
            float acc = sh2[n8][0][lane]+sh2[n8][1][lane]+b1[lane];
            sh1[n8][lane]=leaky(acc);
            __syncwarp();
            float acc2 = b2[lane];
            const float4* w2v = (const float4*)(w2 + lane*32);
#pragma unroll
            for(int q=0;q<8;q++){
                float4 wv=w2v[q];
                acc2 += wv.x*sh1[n8][4*q]+wv.y*sh1[n8][4*q+1]+wv.z*sh1[n8][4*q+2]+wv.w*sh1[n8][4*q+3];
            }
            g_e1[node*32+lane]=leaky(acc2);
        }
    }
}

// ============ k3: edge conv 2 + stats stage 1 (128 x 512) ============
__global__ void __launch_bounds__(512) k_e2s1(const float* __restrict__ feat,
        const float* __restrict__ b1, const float* __restrict__ w2,
        const float* __restrict__ b2){
    extern __shared__ char sm_[];
    const int tid=threadIdx.x, bid=blockIdx.x;
    const int w=tid>>5, lane=tid&31;
    const int n8=w>>1, h=w&1;
    const int node = bid*8 + n8;

    // ---- edge conv 2 ----
    {
        float4* sW  = (float4*)sm_;                         // 32768
        float (*sv)[256]   = (float(*)[256])(sm_+32768);    // 8192
        float (*sh2)[2][32]= (float(*)[2][32])(sm_+40960);  // 2048
        float (*sh1)[32]   = (float(*)[32])(sm_+43008);     // 1024
        for(int t=tid;t<64*32;t+=512) sW[t]=g_w1t2[t];
        for(int t=lane;t<128;t+=32){
            int f = 16*h + (t>>3), k = t&7;
            int nb = g_idx[node*KNN+k];
            sv[n8][f*8+k] = g_e1[nb*32+f];
        }
        __syncthreads();
        float a0=0.f,a1=0.f,a2=0.f,a3=0.f;
        const float4* vv4 = (const float4*)sv[n8];
#pragma unroll
        for(int u=0;u<32;u++){
            int tt = 32*h+u;
            float4 wv = sW[tt*32+lane];
            float4 vv = vv4[tt];
            a0+=wv.x*vv.x; a1+=wv.y*vv.y; a2+=wv.z*vv.z; a3+=wv.w*vv.w;
        }
        sh2[n8][h][lane]=((a0+a1)+(a2+a3));
        __syncthreads();
        if (h==0){
            float acc = sh2[n8][0][lane]+sh2[n8][1][lane]+b1[lane];
            sh1[n8][lane]=leaky(acc);
            __syncwarp();
            float acc2 = b2[lane];
            const float4* w2v = (const float4*)(w2 + lane*32);
#pragma unroll
            for(int q=0;q<8;q++){
                float4 wv=w2v[q];
                acc2 += wv.x*sh1[n8][4*q]+wv.y*sh1[n8][4*q+1]+wv.z*sh1[n8][4*q+2]+wv.w*sh1[n8][4*q+3];
            }
            g_e2[node*32+lane]=leaky(acc2);
        }
    }
    __syncthreads();

    // ---- stats stage 1: per-block (8 nodes) weighted partials ----
    {
        float (*srow)[100] = (float(*)[100])sm_;
        for(int t=tid;t<288;t+=512){
            int f=t%36;
            srow[t/36][f] = fmaf(feat[bid*8*D_IN + t], __ldg(&g_sc[f]), __ldg(&g_sh[f]));
        }
        for(int t=tid;t<256;t+=512) srow[t>>5][36+(t&31)] = g_e1[bid*8*32 + t];
        __syncthreads();
        for(int t=tid;t<256;t+=512) srow[t>>5][68+(t&31)] = g_e2[bid*8*32 + t];
        __syncthreads();
        if (tid < 400){
            int c = tid/100, f = tid%100;
            float acc=0.f;
#pragma unroll
            for(int nd=0;nd<8;nd++){
                int gi = bid*8+nd;
                float v = srow[nd][f];
                float wt = (c<2)? (float)(NN-1-gi) : (float)gi;
                float vv = (c&1)? v*v : v;
                acc += wt*vv;
            }
            g_part[(c*100+f)*128 + bid] = acc;
        }
    }
}

// ==== k4: stats stage 2 + W1p/ssh precompute (100 x 512) ====
__global__ void __launch_bounds__(512) k_stats2(const float* __restrict__ lw1,
        const float* __restrict__ lbng, const float* __restrict__ lbnb){
    __shared__ float red[512];
    __shared__ float sc2[2];
    const int tid=threadIdx.x, f=blockIdx.x;
    int c = tid>>7, idx = tid&127;
    red[tid] = g_part[(c*100+f)*128 + idx];
    __syncthreads();
    for(int o=64;o>0;o>>=1){
        if ((tid&127) < o) red[tid] += red[tid+o];
        __syncthreads();
    }
    if (tid==0){
        const float invP = 1.0f/(float)NPAIR;
        float m1=red[0]*invP,   q1=red[128]*invP;
        float m2=red[256]*invP, q2=red[384]*invP;
        float s1 = rsqrtf(q1-m1*m1+EPSV);
        float s2 = rsqrtf(q2-m2*m2+EPSV);
        float scA = lbng[f]*s1;
        float scB = lbng[100+f]*s2;
        sc2[0]=scA; sc2[1]=scB;
        g_ssh[f]     = lbnb[f]    -m1*scA;
        g_ssh[100+f] = lbnb[100+f]-m2*scB;
    }
    __syncthreads();
    if (tid < 64){
        int half = tid>>5, o = tid&31;
        int fe = f + 100*half;
        g_W1p[fe*32+o] = lw1[o*200+fe]*sc2[half];
    }
}

// ============ k5: A,B projections + coalesced bias (128 x 512) ============
__global__ void __launch_bounds__(512) k_abk(const float* __restrict__ feat,
        const float* __restrict__ lw1, const float* __restrict__ lb1){
    extern __shared__ char sm_[];
    const int tid=threadIdx.x, bid=blockIdx.x;
    const int w=tid>>5, lane=tid&31;
    const int n8=w>>1, h=w&1;
    const int node = bid*8 + n8;

    float* sWp = (float*)sm_;                 // 6400
    float* sshs = sWp + 6400;                 // 200
    float* scc = sshs + 200;                  // 32
    float (*srow)[100]  = (float(*)[100])(scc + 32);          // 800
    float (*spa)[2][32] = (float(*)[2][32])(scc + 32 + 800);  // 512
    float (*spb)[2][32] = (float(*)[2][32])(scc + 32 + 1312); // 512

    {
        float4* d4 = (float4*)sWp;
        const float4* s4 = (const float4*)g_W1p;
        for(int t=tid;t<1600;t+=512) d4[t]=s4[t];
    }
    if (tid < 200) sshs[tid]=g_ssh[tid];
    for(int t=tid;t<288;t+=512){
        int f=t%36;
        srow[t/36][f] = fmaf(feat[bid*8*D_IN + t], __ldg(&g_sc[f]), __ldg(&g_sh[f]));
    }
    for(int t=tid;t<256;t+=512) srow[t>>5][36+(t&31)] = g_e1[bid*8*32 + t];
    for(int t=tid;t<256;t+=512) srow[t>>5][68+(t&31)] = g_e2[bid*8*32 + t];
    __syncthreads();

#pragma unroll
    for(int oo=0;oo<2;oo++){
        int o = w*2 + oo;
        float acc = 0.f;
#pragma unroll
        for(int k=0;k<7;k++){
            int f = lane + 32*k;
            if (f < 200) acc += lw1[o*200+f]*sshs[f];
        }
#pragma unroll
        for(int off=16;off>0;off>>=1) acc += __shfl_xor_sync(0xffffffffu,acc,off);
        if (lane==0) scc[o]=lb1[o]+acc;
    }
    __syncthreads();

    float a=0.f, b=0.f;
    for(int u=0;u<50;u++){
        int f = 50*h+u;
        float v=srow[n8][f];
        a += v*sWp[f*32+lane];
        b += v*sWp[(100+f)*32+lane];
    }
    spa[n8][h][lane]=a; spb[n8][h][lane]=b;
    __syncthreads();
    if (h==0){
        g_A[node*32+lane]=spa[n8][0][lane]+spa[n8][1][lane]+scc[lane];
        g_B[node*32+lane]=spb[n8][0][lane]+spb[n8][1][lane];
    }
}

// =====================================================================
// Pair kernel v3: 2D tiling (16 i x 64 j per CTA), A/B windows in SMEM.
// 544 CTAs; warp tile = (1 i) x (16 j); predicated triangular stores.
// =====================================================================
#define PSTR 36
__global__ void __launch_bounds__(256,3) k_pairs_tc(
        const float* __restrict__ lw2, const float* __restrict__ lb2,
        const float* __restrict__ lw3, const float* __restrict__ lb3,
        float* __restrict__ out){
    __shared__ float sA[16*PSTR];             // 2304 B
    __shared__ float sB[64*PSTR];             // 9216 B
    __shared__ float sh1s[8][16*PSTR];        // 18432 B
    __shared__ float sW3[64], sB3[2];
    const int warp = threadIdx.x>>5, lane = threadIdx.x&31;
    const int g = lane>>2, tig = lane&3;

    if (threadIdx.x<64) sW3[threadIdx.x]=lw3[threadIdx.x];
    if (threadIdx.x<2)  sB3[threadIdx.x]=lb3[threadIdx.x];

    // decode blockIdx -> (jt, it):  count(jt)=4(jt+1), base(jt)=2*jt*(jt+1)
    int b = blockIdx.x;
    int jt = 0;
    while (2*(jt+1)*(jt+2) <= b) jt++;
    const int it = b - 2*jt*(jt+1);
    const int i0 = it*16, j0 = jt*64;

    // W2 fragments (single rounded tf32 term)
    uint32_t Bhi[4][4][2];
#pragma unroll
    for(int s=0;s<4;s++){
#pragma unroll
        for(int nt=0;nt<4;nt++){
            int o = nt*8 + g;
            Bhi[s][nt][0] = to_tf32(__ldg(&lw2[o*32 + s*8 + tig]));
            Bhi[s][nt][1] = to_tf32(__ldg(&lw2[o*32 + s*8 + tig + 4]));
        }
    }
    float b2r[4][2];
#pragma unroll
    for(int nt=0;nt<4;nt++){
        b2r[nt][0]=__ldg(&lb2[nt*8+2*tig]);
        b2r[nt][1]=__ldg(&lb2[nt*8+2*tig+1]);
    }

    // load A window (16 rows) and B window (64 rows), padded stride
    for(int t=threadIdx.x; t<128; t+=256){
        float4 v = *(const float4*)(g_A + i0*32 + t*4);
        *(float4*)(sA + (t>>3)*PSTR + (t&7)*4) = v;
    }
    for(int t=threadIdx.x; t<512; t+=256){
        float4 v = *(const float4*)(g_B + j0*32 + t*4);
        *(float4*)(sB + (t>>3)*PSTR + (t&7)*4) = v;
    }
    __syncthreads();

    float* sh = sh1s[warp];
    const int pr = lane>>1, half = lane&1;

#pragma unroll 1
    for(int u=0; u<8; u++){
        const int T  = warp*8 + u;
        const int di = T>>2, jq = T&3;
        const int i  = i0 + di;
        const int jb = j0 + jq*16;
        if (jb + 15 <= i) continue;        // tile fully below diagonal

        // ---- stage h1[16][32] from SMEM windows ----
        {
            const float4* a4 = (const float4*)(sA + di*PSTR + half*16);
            const float4* b4 = (const float4*)(sB + (jq*16+pr)*PSTR + half*16);
            float4* row = (float4*)(sh + pr*PSTR + half*16);
#pragma unroll
            for(int q=0;q<4;q++){
                float4 av=a4[q], bv=b4[q];
                float4 hv;
                hv.x=leaky(av.x+bv.x); hv.y=leaky(av.y+bv.y);
                hv.z=leaky(av.z+bv.z); hv.w=leaky(av.w+bv.w);
                row[q]=hv;
            }
        }
        __syncwarp();

        float C[4][4];
#pragma unroll
        for(int nt=0;nt<4;nt++){
            C[nt][0]=b2r[nt][0]; C[nt][1]=b2r[nt][1];
            C[nt][2]=b2r[nt][0]; C[nt][3]=b2r[nt][1];
        }
#pragma unroll
        for(int s=0;s<4;s++){
            const int f0=s*8+tig, f1=f0+4;
            float v0 = sh[ g   *PSTR + f0];
            float v1 = sh[(g+8)*PSTR + f0];
            float v2 = sh[ g   *PSTR + f1];
            float v3 = sh[(g+8)*PSTR + f1];
            uint32_t Ah[4];
            Ah[0]=to_tf32(v0); Ah[1]=to_tf32(v1);
            Ah[2]=to_tf32(v2); Ah[3]=to_tf32(v3);
#pragma unroll
            for(int nt=0;nt<4;nt++){
                mma_tf32(C[nt], Ah, Bhi[s][nt]);
            }
        }

        float y00=0.f,y01=0.f,y10=0.f,y11=0.f;
#pragma unroll
        for(int nt=0;nt<4;nt++){
            float w300=sW3[nt*8+2*tig],    w301=sW3[nt*8+2*tig+1];
            float w310=sW3[32+nt*8+2*tig], w311=sW3[32+nt*8+2*tig+1];
            float h0=leaky(C[nt][0]), h1v=leaky(C[nt][1]);
            float h2=leaky(C[nt][2]), h3=leaky(C[nt][3]);
            y00 += h0*w300 + h1v*w301;
            y01 += h0*w310 + h1v*w311;
            y10 += h2*w300 + h3*w301;
            y11 += h2*w310 + h3*w311;
        }
        y00 += __shfl_xor_sync(0xffffffffu,y00,1); y00 += __shfl_xor_sync(0xffffffffu,y00,2);
        y01 += __shfl_xor_sync(0xffffffffu,y01,1); y01 += __shfl_xor_sync(0xffffffffu,y01,2);
        y10 += __shfl_xor_sync(0xffffffffu,y10,1); y10 += __shfl_xor_sync(0xffffffffu,y10,2);
        y11 += __shfl_xor_sync(0xffffffffu,y11,1); y11 += __shfl_xor_sync(0xffffffffu,y11,2);
        if (tig==0){
            const int rs = rowstart(i);
            int j1 = jb + g;
            if (j1 > i)
                *(float2*)(out + (size_t)(rs + j1 - i - 1)*2) = make_float2(y00+sB3[0], y01+sB3[1]);
            int j2 = jb + g + 8;
            if (j2 > i)
                *(float2*)(out + (size_t)(rs + j2 - i - 1)*2) = make_float2(y10+sB3[0], y11+sB3[1]);
        }
        __syncwarp();
    }
}

// ---------------- launch: 6 kernels ----------------
extern "C" void kernel_launch(void* const* d_in, const int* in_sizes, int n_in,
                              void* d_out, int out_size){
    const float* feat   = (const float*)d_in[0];
    const float* bn_g   = (const float*)d_in[1];
    const float* bn_b   = (const float*)d_in[2];
    const float* ec1_w1 = (const float*)d_in[3];
    const float* ec1_b1 = (const float*)d_in[4];
    const float* ec1_w2 = (const float*)d_in[5];
    const float* ec1_b2 = (const float*)d_in[6];
    const float* ec2_w1 = (const float*)d_in[7];
    const float* ec2_b1 = (const float*)d_in[8];
    const float* ec2_w2 = (const float*)d_in[9];
    const float* ec2_b2 = (const float*)d_in[10];
    const float* lbn_g  = (const float*)d_in[11];
    const float* lbn_b  = (const float*)d_in[12];
    const float* l_w1   = (const float*)d_in[13];
    const float* l_b1   = (const float*)d_in[14];
    const float* l_w2   = (const float*)d_in[15];
    const float* l_b2   = (const float*)d_in[16];
    const float* l_w3   = (const float*)d_in[17];
    const float* l_b3   = (const float*)d_in[18];
    float* out = (float*)d_out;

    static int attr_done = 0;
    if (!attr_done){
        cudaFuncSetAttribute(k_knn_e1, cudaFuncAttributeMaxDynamicSharedMemorySize, 49152);
        cudaFuncSetAttribute(k_e2s1,   cudaFuncAttributeMaxDynamicSharedMemorySize, 45056);
        cudaFuncSetAttribute(k_abk,    cudaFuncAttributeMaxDynamicSharedMemorySize, 36864);
        attr_done = 1;
    }

    k_stats  <<<82, 512>>>(feat, ec1_w1, ec2_w1, bn_g, bn_b, out + (size_t)2*NPAIR);
    k_knn_e1 <<<128, 512, 49152>>>(feat, ec1_b1, ec1_w2, ec1_b2);
    k_e2s1   <<<128, 512, 45056>>>(feat, ec2_b1, ec2_w2, ec2_b2);
    k_stats2 <<<100, 512>>>(l_w1, lbn_g, lbn_b);
    k_abk    <<<128, 512, 36864>>>(feat, l_w1, l_b1);
    k_pairs_tc<<<544, 256>>>(l_w2, l_b2, l_w3, l_b3, out);
}

// round 17
// speedup vs baseline: 1.2672x; 1.0688x over previous
#include <cuda_runtime.h>
#include <math.h>
#include <stdint.h>

#define NN      1024
#define KNN     8
#define D_IN    36
#define NPAIR   (NN*(NN-1)/2)    // 523776
#define EPSV    1e-5f
#define SLOPE   0.01f

// ---------------- device scratch ----------------
__device__ float g_e1[NN*32];             // edge conv 1 out
__device__ float g_e2[NN*32];             // edge conv 2 out
__device__ float g_sc[D_IN], g_sh[D_IN];  // folded feature-BN: v = x*sc + sh
__device__ int   g_idx[NN*KNN];
__device__ float4 g_w1t1[72*32];          // ec1_w1 packed: [tt][o]
__device__ float4 g_w1t2[64*32];
__device__ float g_part[4*100*128];       // pair-stats partials
__device__ float g_W1p[200*32];           // BN-scaled l_w1 (written by k_stats2)
__device__ float g_ssh[200];              // pair-BN shift (for bias fold)
__device__ float g_A[NN*32];
__device__ float g_B[NN*32];

__device__ __forceinline__ float leaky(float x){ return fmaxf(x, SLOPE*x); }
__device__ __forceinline__ int rowstart(int i){ return i*NN - ((i*(i+1))>>1); }

// cp.async helpers (16B)
__device__ __forceinline__ void cpa16(void* dst, const void* src){
    unsigned sdst = (unsigned)__cvta_generic_to_shared(dst);
    asm volatile("cp.async.cg.shared.global [%0], [%1], 16;"::"r"(sdst),"l"(src));
}
__device__ __forceinline__ void cpa_wait(){
    asm volatile("cp.async.commit_group;");
    asm volatile("cp.async.wait_group 0;");
}

// tf32 helpers
__device__ __forceinline__ uint32_t to_tf32(float v){
    uint32_t r; asm("cvt.rna.tf32.f32 %0,%1;":"=r"(r):"f"(v)); return r;
}
__device__ __forceinline__ void mma_tf32(float* C, const uint32_t* A, const uint32_t* B){
    asm volatile(
      "mma.sync.aligned.m16n8k8.row.col.f32.tf32.tf32.f32 "
      "{%0,%1,%2,%3},{%4,%5,%6,%7},{%8,%9},{%0,%1,%2,%3};"
      : "+f"(C[0]),"+f"(C[1]),"+f"(C[2]),"+f"(C[3])
      : "r"(A[0]),"r"(A[1]),"r"(A[2]),"r"(A[3]),"r"(B[0]),"r"(B[1]));
}

// ==== k1: BN stats+fold (0..35) | weight pack (36..71) | cells (72..81) ====
__global__ void __launch_bounds__(512) k_stats(const float* __restrict__ feat,
        const float* __restrict__ e1w1, const float* __restrict__ e2w1,
        const float* __restrict__ bng,  const float* __restrict__ bnb,
        float* __restrict__ out_cells){
    __shared__ float ss[512], sq[512];
    int tid=threadIdx.x, bid=blockIdx.x;
    if (bid < 36){
        int f = bid;
        float s=0.f, q=0.f;
        for(int i=tid;i<NN;i+=512){ float v=feat[i*D_IN+f]; s+=v; q+=v*v; }
        ss[tid]=s; sq[tid]=q; __syncthreads();
        for(int o=256;o>0;o>>=1){
            if(tid<o){ ss[tid]+=ss[tid+o]; sq[tid]+=sq[tid+o]; }
            __syncthreads();
        }
        if(tid==0){
            float m=ss[0]*(1.f/NN);
            float var=sq[0]*(1.f/NN)-m*m;
            float sc = rsqrtf(var+EPSV)*bng[f];
            g_sc[f]=sc;
            g_sh[f]=bnb[f]-m*sc;
        }
    } else if (bid < 72){
        int t = (bid-36)*512 + tid;
        if (t < 72*32){ int tt=t>>5, o=t&31; g_w1t1[t] = *(const float4*)(e1w1 + o*288 + 4*tt); }
        if (t < 64*32){ int tt=t>>5, o=t&31; g_w1t2[t] = *(const float4*)(e2w1 + o*256 + 4*tt); }
    } else {
        int t = (bid-72)*512 + tid;
        if (t < NN*5){
            int i=t/5, c=t%5;
            out_cells[t] = feat[i*D_IN+c];
        }
    }
}

// ============ k2: kNN + edge conv 1 fused (128 x 512) ============
__global__ void __launch_bounds__(512) k_knn_e1(const float* __restrict__ feat,
        const float* __restrict__ b1,
        const float* __restrict__ w2, const float* __restrict__ b2){
    extern __shared__ char sm_[];
    const int tid=threadIdx.x, bid=blockIdx.x;
    const int w=tid>>5, lane=tid&31;
    const int n8=w>>1, h=w&1;
    const int node = bid*8 + n8;

    // ---- kNN (2 warps per node); coords normalized inline ----
    {
        float4* sxy = (float4*)sm_;
        float  (*skd)[2][8] = (float(*)[2][8])(sm_+16384);
        int    (*ski)[2][8] = (int  (*)[2][8])(sm_+16896);
        float4 sc4, sh4;
        sc4.x=__ldg(&g_sc[0]); sc4.y=__ldg(&g_sc[1]); sc4.z=__ldg(&g_sc[2]); sc4.w=__ldg(&g_sc[3]);
        sh4.x=__ldg(&g_sh[0]); sh4.y=__ldg(&g_sh[1]); sh4.z=__ldg(&g_sh[2]); sh4.w=__ldg(&g_sh[3]);
        for(int t=tid;t<NN;t+=512){
            float4 r = *(const float4*)(feat + t*D_IN);
            float4 v;
            v.x=fmaf(r.x,sc4.x,sh4.x); v.y=fmaf(r.y,sc4.y,sh4.y);
            v.z=fmaf(r.z,sc4.z,sh4.z); v.w=fmaf(r.w,sc4.w,sh4.w);
            sxy[t]=v;
        }
        __syncthreads();
        const float4 xi = sxy[node];
        float d8[8]; int id8[8];
#pragma unroll
        for(int k=0;k<8;k++){ d8[k]=3.4e38f; id8[k]=0x7fffffff; }
        float kth = 3.4e38f; int kthi = 0x7fffffff;
        for(int it=0; it<16; it++){
            int j = 512*h + it*32 + lane;
            float4 xj = sxy[j];
            float cd = fabsf(xi.x-xj.x)+fabsf(xi.y-xj.y)+fabsf(xi.z-xj.z)+fabsf(xi.w-xj.w);
            int ci = j;
            if (cd < kth || (cd==kth && ci < kthi)){
#pragma unroll
                for(int k=0;k<8;k++){
                    bool sw = (cd < d8[k]) || (cd==d8[k] && ci < id8[k]);
                    float td = sw ? d8[k] : cd; int ti = sw ? id8[k] : ci;
                    d8[k]  = sw ? cd : d8[k]; id8[k] = sw ? ci : id8[k];
                    cd=td; ci=ti;
                }
                kth = d8[7]; kthi = id8[7];
            }
        }
        for(int r=0;r<8;r++){
            float bd=d8[0]; int bi=id8[0];
#pragma unroll
            for(int off=16;off>0;off>>=1){
                float od=__shfl_xor_sync(0xffffffffu,bd,off);
                int   oi=__shfl_xor_sync(0xffffffffu,bi,off);
                if (od<bd || (od==bd && oi<bi)){ bd=od; bi=oi; }
            }
            if (lane==0){ skd[n8][h][r]=bd; ski[n8][h][r]=bi; }
            if (id8[0]==bi){
#pragma unroll
                for(int k=0;k<7;k++){ d8[k]=d8[k+1]; id8[k]=id8[k+1]; }
                d8[7]=3.4e38f; id8[7]=0x7fffffff;
            }
        }
        __syncthreads();
        if (h==0){
            float md = 3.4e38f; int mi = 0x7fffffff;
            if (lane < 16){ md = skd[n8][lane>>3][lane&7]; mi = ski[n8][lane>>3][lane&7]; }
            for(int r=0;r<8;r++){
                float bd=md; int bi=mi;
#pragma unroll
                for(int off=16;off>0;off>>=1){
                    float od=__shfl_xor_sync(0xffffffffu,bd,off);
                    int   oi=__shfl_xor_sync(0xffffffffu,bi,off);
                    if (od<bd || (od==bd && oi<bi)){ bd=od; bi=oi; }
                }
                if (lane==0) g_idx[node*KNN+r]=bi;
                if (md==bd && mi==bi){ md=3.4e38f; mi=0x7fffffff; }
            }
        }
    }
    __syncthreads();

    // ---- edge conv 1 (cp.async weight staging; gather normalizes inline) ----
    {
        float4* sW  = (float4*)sm_;
        float (*sv)[288]   = (float(*)[288])(sm_+36864);
        float (*sh2)[2][32]= (float(*)[2][32])(sm_+46080);
        float (*sh1)[32]   = (float(*)[32])(sm_+48128);
        for(int t=tid;t<72*32;t+=512) cpa16(&sW[t], &g_w1t1[t]);
        for(int t=lane;t<144;t+=32){
            int f = 18*h + (t>>3), k = t&7;
            int nb = g_idx[node*KNN+k];
            sv[n8][f*8+k] = fmaf(feat[nb*D_IN+f], __ldg(&g_sc[f]), __ldg(&g_sh[f]));
        }
        cpa_wait();
        __syncthreads();
        float a0=0.f,a1=0.f,a2=0.f,a3=0.f;
        const float4* vv4 = (const float4*)sv[n8];
#pragma unroll
        for(int u=0;u<36;u++){
            int tt = 36*h+u;
            float4 wv = sW[tt*32+lane];
            float4 vv = vv4[tt];
            a0+=wv.x*vv.x; a1+=wv.y*vv.y; a2+=wv.z*vv.z; a3+=wv.w*vv.w;
        }
        sh2[n8][h][lane]=((a0+a1)+(a2+a3));
        __syncthreads();
        if (h==0){
            float acc = sh2[n8][0][lane]+sh2[n8][1][lane]+b1[lane];
            sh1[n8][lane]=leaky(acc);
            __syncwarp();
            float acc2 = b2[lane];
            const float4* w2v = (const float4*)(w2 + lane*32);
#pragma unroll
            for(int q=0;q<8;q++){
                float4 wv=w2v[q];
                acc2 += wv.x*sh1[n8][4*q]+wv.y*sh1[n8][4*q+1]+wv.z*sh1[n8][4*q+2]+wv.w*sh1[n8][4*q+3];
            }
            g_e1[node*32+lane]=leaky(acc2);
        }
    }
}

// ============ k3: edge conv 2 + stats stage 1 (128 x 512) ============
__global__ void __launch_bounds__(512) k_e2s1(const float* __restrict__ feat,
        const float* __restrict__ b1, const float* __restrict__ w2,
        const float* __restrict__ b2){
    extern __shared__ char sm_[];
    const int tid=threadIdx.x, bid=blockIdx.x;
    const int w=tid>>5, lane=tid&31;
    const int n8=w>>1, h=w&1;
    const int node = bid*8 + n8;

    // ---- edge conv 2 (cp.async weight staging) ----
    {
        float4* sW  = (float4*)sm_;                         // 32768
        float (*sv)[256]   = (float(*)[256])(sm_+32768);    // 8192
        float (*sh2)[2][32]= (float(*)[2][32])(sm_+40960);  // 2048
        float (*sh1)[32]   = (float(*)[32])(sm_+43008);     // 1024
        for(int t=tid;t<64*32;t+=512) cpa16(&sW[t], &g_w1t2[t]);
        for(int t=lane;t<128;t+=32){
            int f = 16*h + (t>>3), k = t&7;
            int nb = g_idx[node*KNN+k];
            sv[n8][f*8+k] = g_e1[nb*32+f];
        }
        cpa_wait();
        __syncthreads();
        float a0=0.f,a1=0.f,a2=0.f,a3=0.f;
        const float4* vv4 = (const float4*)sv[n8];
#pragma unroll
        for(int u=0;u<32;u++){
            int tt = 32*h+u;
            float4 wv = sW[tt*32+lane];
            float4 vv = vv4[tt];
            a0+=wv.x*vv.x; a1+=wv.y*vv.y; a2+=wv.z*vv.z; a3+=wv.w*vv.w;
        }
        sh2[n8][h][lane]=((a0+a1)+(a2+a3));
        __syncthreads();
        if (h==0){
            float acc = sh2[n8][0][lane]+sh2[n8][1][lane]+b1[lane];
            sh1[n8][lane]=leaky(acc);
            __syncwarp();
            float acc2 = b2[lane];
            const float4* w2v = (const float4*)(w2 + lane*32);
#pragma unroll
            for(int q=0;q<8;q++){
                float4 wv=w2v[q];
                acc2 += wv.x*sh1[n8][4*q]+wv.y*sh1[n8][4*q+1]+wv.z*sh1[n8][4*q+2]+wv.w*sh1[n8][4*q+3];
            }
            g_e2[node*32+lane]=leaky(acc2);
        }
    }
    __syncthreads();

    // ---- stats stage 1: per-block (8 nodes) weighted partials ----
    {
        float (*srow)[100] = (float(*)[100])sm_;
        for(int t=tid;t<288;t+=512){
            int f=t%36;
            srow[t/36][f] = fmaf(feat[bid*8*D_IN + t], __ldg(&g_sc[f]), __ldg(&g_sh[f]));
        }
        for(int t=tid;t<256;t+=512) srow[t>>5][36+(t&31)] = g_e1[bid*8*32 + t];
        __syncthreads();
        for(int t=tid;t<256;t+=512) srow[t>>5][68+(t&31)] = g_e2[bid*8*32 + t];
        __syncthreads();
        if (tid < 400){
            int c = tid/100, f = tid%100;
            float acc=0.f;
#pragma unroll
            for(int nd=0;nd<8;nd++){
                int gi = bid*8+nd;
                float v = srow[nd][f];
                float wt = (c<2)? (float)(NN-1-gi) : (float)gi;
                float vv = (c&1)? v*v : v;
                acc += wt*vv;
            }
            g_part[(c*100+f)*128 + bid] = acc;
        }
    }
}

// ==== k4: stats stage 2 + W1p/ssh precompute (100 x 512) ====
__global__ void __launch_bounds__(512) k_stats2(const float* __restrict__ lw1,
        const float* __restrict__ lbng, const float* __restrict__ lbnb){
    __shared__ float red[512];
    __shared__ float sc2[2];
    const int tid=threadIdx.x, f=blockIdx.x;
    int c = tid>>7, idx = tid&127;
    red[tid] = g_part[(c*100+f)*128 + idx];
    __syncthreads();
    for(int o=64;o>0;o>>=1){
        if ((tid&127) < o) red[tid] += red[tid+o];
        __syncthreads();
    }
    if (tid==0){
        const float invP = 1.0f/(float)NPAIR;
        float m1=red[0]*invP,   q1=red[128]*invP;
        float m2=red[256]*invP, q2=red[384]*invP;
        float s1 = rsqrtf(q1-m1*m1+EPSV);
        float s2 = rsqrtf(q2-m2*m2+EPSV);
        float scA = lbng[f]*s1;
        float scB = lbng[100+f]*s2;
        sc2[0]=scA; sc2[1]=scB;
        g_ssh[f]     = lbnb[f]    -m1*scA;
        g_ssh[100+f] = lbnb[100+f]-m2*scB;
    }
    __syncthreads();
    if (tid < 64){
        int half = tid>>5, o = tid&31;
        int fe = f + 100*half;
        g_W1p[fe*32+o] = lw1[o*200+fe]*sc2[half];
    }
}

// ============ k5: A,B projections + coalesced bias (128 x 512) ============
__global__ void __launch_bounds__(512) k_abk(const float* __restrict__ feat,
        const float* __restrict__ lw1, const float* __restrict__ lb1){
    extern __shared__ char sm_[];
    const int tid=threadIdx.x, bid=blockIdx.x;
    const int w=tid>>5, lane=tid&31;
    const int n8=w>>1, h=w&1;
    const int node = bid*8 + n8;

    float* sWp = (float*)sm_;                 // 6400
    float* sshs = sWp + 6400;                 // 200
    float* scc = sshs + 200;                  // 32
    float (*srow)[100]  = (float(*)[100])(scc + 32);          // 800
    float (*spa)[2][32] = (float(*)[2][32])(scc + 32 + 800);  // 512
    float (*spb)[2][32] = (float(*)[2][32])(scc + 32 + 1312); // 512

    {
        float4* d4 = (float4*)sWp;
        const float4* s4 = (const float4*)g_W1p;
        for(int t=tid;t<1600;t+=512) cpa16(&d4[t], &s4[t]);
    }
    if (tid < 200) sshs[tid]=g_ssh[tid];
    for(int t=tid;t<288;t+=512){
        int f=t%36;
        srow[t/36][f] = fmaf(feat[bid*8*D_IN + t], __ldg(&g_sc[f]), __ldg(&g_sh[f]));
    }
    for(int t=tid;t<256;t+=512) srow[t>>5][36+(t&31)] = g_e1[bid*8*32 + t];
    for(int t=tid;t<256;t+=512) srow[t>>5][68+(t&31)] = g_e2[bid*8*32 + t];
    cpa_wait();
    __syncthreads();

#pragma unroll
    for(int oo=0;oo<2;oo++){
        int o = w*2 + oo;
        float acc = 0.f;
#pragma unroll
        for(int k=0;k<7;k++){
            int f = lane + 32*k;
            if (f < 200) acc += lw1[o*200+f]*sshs[f];
        }
#pragma unroll
        for(int off=16;off>0;off>>=1) acc += __shfl_xor_sync(0xffffffffu,acc,off);
        if (lane==0) scc[o]=lb1[o]+acc;
    }
    __syncthreads();

    float a=0.f, b=0.f;
    for(int u=0;u<50;u++){
        int f = 50*h+u;
        float v=srow[n8][f];
        a += v*sWp[f*32+lane];
        b += v*sWp[(100+f)*32+lane];
    }
    spa[n8][h][lane]=a; spb[n8][h][lane]=b;
    __syncthreads();
    if (h==0){
        g_A[node*32+lane]=spa[n8][0][lane]+spa[n8][1][lane]+scc[lane];
        g_B[node*32+lane]=spb[n8][0][lane]+spb[n8][1][lane];
    }
}

// =====================================================================
// Pair kernel v4: 2D tiling + DIRECT fragment compute (no h1 staging).
// 544 CTAs; warp tile = (1 i) x (16 j); predicated triangular stores.
// =====================================================================
#define PSTR 36
__global__ void __launch_bounds__(256,3) k_pairs_tc(
        const float* __restrict__ lw2, const float* __restrict__ lb2,
        const float* __restrict__ lw3, const float* __restrict__ lb3,
        float* __restrict__ out){
    __shared__ float sA[16*PSTR];             // 2304 B
    __shared__ float sB[64*PSTR];             // 9216 B
    __shared__ float sW3[64], sB3[2];
    const int warp = threadIdx.x>>5, lane = threadIdx.x&31;
    const int g = lane>>2, tig = lane&3;

    if (threadIdx.x<64) sW3[threadIdx.x]=lw3[threadIdx.x];
    if (threadIdx.x<2)  sB3[threadIdx.x]=lb3[threadIdx.x];

    // decode blockIdx -> (jt, it):  count(jt)=4(jt+1), base(jt)=2*jt*(jt+1)
    int b = blockIdx.x;
    int jt = 0;
    while (2*(jt+1)*(jt+2) <= b) jt++;
    const int it = b - 2*jt*(jt+1);
    const int i0 = it*16, j0 = jt*64;

    // W2 fragments (single rounded tf32 term)
    uint32_t Bhi[4][4][2];
#pragma unroll
    for(int s=0;s<4;s++){
#pragma unroll
        for(int nt=0;nt<4;nt++){
            int o = nt*8 + g;
            Bhi[s][nt][0] = to_tf32(__ldg(&lw2[o*32 + s*8 + tig]));
            Bhi[s][nt][1] = to_tf32(__ldg(&lw2[o*32 + s*8 + tig + 4]));
        }
    }
    float b2r[4][2];
#pragma unroll
    for(int nt=0;nt<4;nt++){
        b2r[nt][0]=__ldg(&lb2[nt*8+2*tig]);
        b2r[nt][1]=__ldg(&lb2[nt*8+2*tig+1]);
    }

    // load A window (16 rows) and B window (64 rows), padded stride
    for(int t=threadIdx.x; t<128; t+=256){
        float4 v = *(const float4*)(g_A + i0*32 + t*4);
        *(float4*)(sA + (t>>3)*PSTR + (t&7)*4) = v;
    }
    for(int t=threadIdx.x; t<512; t+=256){
        float4 v = *(const float4*)(g_B + j0*32 + t*4);
        *(float4*)(sB + (t>>3)*PSTR + (t&7)*4) = v;
    }
    __syncthreads();

#pragma unroll 1
    for(int u=0; u<8; u++){
        const int T  = warp*8 + u;
        const int di = T>>2, jq = T&3;
        const int i  = i0 + di;
        const int jb = j0 + jq*16;
        if (jb + 15 <= i) continue;        // tile fully below diagonal

        const float* Arow  = sA + di*PSTR;
        const float* Brow0 = sB + (jq*16 + g)*PSTR;      // pair row g
        const float* Brow1 = Brow0 + 8*PSTR;             // pair row g+8

        float C[4][4];
#pragma unroll
        for(int nt=0;nt<4;nt++){
            C[nt][0]=b2r[nt][0]; C[nt][1]=b2r[nt][1];
            C[nt][2]=b2r[nt][0]; C[nt][3]=b2r[nt][1];
        }
#pragma unroll
        for(int s=0;s<4;s++){
            const int f0=s*8+tig, f1=f0+4;
            float aA0 = Arow[f0], aA1 = Arow[f1];
            uint32_t Ah[4];
            Ah[0]=to_tf32(leaky(aA0 + Brow0[f0]));
            Ah[1]=to_tf32(leaky(aA0 + Brow1[f0]));
            Ah[2]=to_tf32(leaky(aA1 + Brow0[f1]));
            Ah[3]=to_tf32(leaky(aA1 + Brow1[f1]));
#pragma unroll
            for(int nt=0;nt<4;nt++){
                mma_tf32(C[nt], Ah, Bhi[s][nt]);
            }
        }

        float y00=0.f,y01=0.f,y10=0.f,y11=0.f;
#pragma unroll
        for(int nt=0;nt<4;nt++){
            float w300=sW3[nt*8+2*tig],    w301=sW3[nt*8+2*tig+1];
            float w310=sW3[32+nt*8+2*tig], w311=sW3[32+nt*8+2*tig+1];
            float h0=leaky(C[nt][0]), h1v=leaky(C[nt][1]);
            float h2=leaky(C[nt][2]), h3=leaky(C[nt][3]);
            y00 += h0*w300 + h1v*w301;
            y01 += h0*w310 + h1v*w311;
            y10 += h2*w300 + h3*w301;
            y11 += h2*w310 + h3*w311;
        }
        y00 += __shfl_xor_sync(0xffffffffu,y00,1); y00 += __shfl_xor_sync(0xffffffffu,y00,2);
        y01 += __shfl_xor_sync(0xffffffffu,y01,1); y01 += __shfl_xor_sync(0xffffffffu,y01,2);
        y10 += __shfl_xor_sync(0xffffffffu,y10,1); y10 += __shfl_xor_sync(0xffffffffu,y10,2);
        y11 += __shfl_xor_sync(0xffffffffu,y11,1); y11 += __shfl_xor_sync(0xffffffffu,y11,2);
        if (tig==0){
            const int rs = rowstart(i);
            int j1 = jb + g;
            if (j1 > i)
                *(float2*)(out + (size_t)(rs + j1 - i - 1)*2) = make_float2(y00+sB3[0], y01+sB3[1]);
            int j2 = jb + g + 8;
            if (j2 > i)
                *(float2*)(out + (size_t)(rs + j2 - i - 1)*2) = make_float2(y10+sB3[0], y11+sB3[1]);
        }
    }
}

// ---------------- launch: 6 kernels ----------------
extern "C" void kernel_launch(void* const* d_in, const int* in_sizes, int n_in,
                              void* d_out, int out_size){
    const float* feat   = (const float*)d_in[0];
    const float* bn_g   = (const float*)d_in[1];
    const float* bn_b   = (const float*)d_in[2];
    const float* ec1_w1 = (const float*)d_in[3];
    const float* ec1_b1 = (const float*)d_in[4];
    const float* ec1_w2 = (const float*)d_in[5];
    const float* ec1_b2 = (const float*)d_in[6];
    const float* ec2_w1 = (const float*)d_in[7];
    const float* ec2_b1 = (const float*)d_in[8];
    const float* ec2_w2 = (const float*)d_in[9];
    const float* ec2_b2 = (const float*)d_in[10];
    const float* lbn_g  = (const float*)d_in[11];
    const float* lbn_b  = (const float*)d_in[12];
    const float* l_w1   = (const float*)d_in[13];
    const float* l_b1   = (const float*)d_in[14];
    const float* l_w2   = (const float*)d_in[15];
    const float* l_b2   = (const float*)d_in[16];
    const float* l_w3   = (const float*)d_in[17];
    const float* l_b3   = (const float*)d_in[18];
    float* out = (float*)d_out;

    static int attr_done = 0;
    if (!attr_done){
        cudaFuncSetAttribute(k_knn_e1, cudaFuncAttributeMaxDynamicSharedMemorySize, 49152);
        cudaFuncSetAttribute(k_e2s1,   cudaFuncAttributeMaxDynamicSharedMemorySize, 45056);
        cudaFuncSetAttribute(k_abk,    cudaFuncAttributeMaxDynamicSharedMemorySize, 36864);
        attr_done = 1;
    }

    k_stats  <<<82, 512>>>(feat, ec1_w1, ec2_w1, bn_g, bn_b, out + (size_t)2*NPAIR);
    k_knn_e1 <<<128, 512, 49152>>>(feat, ec1_b1, ec1_w2, ec1_b2);
    k_e2s1   <<<128, 512, 45056>>>(feat, ec2_b1, ec2_w2, ec2_b2);
    k_stats2 <<<100, 512>>>(l_w1, lbn_g, lbn_b);
    k_abk    <<<128, 512, 36864>>>(feat, l_w1, l_b1);
    k_pairs_tc<<<544, 256>>>(l_w2, l_b2, l_w3, l_b3, out);
}